// round 13
// baseline (speedup 1.0000x reference)
#include <cuda_runtime.h>
#include <cstdint>

// Problem constants
#define BB   8
#define SS   1024
#define NXX  1024
#define HH   16
#define DHH  64
#define NVV  49
#define NTT  14
#define NSS  1087          // 14 + 49 + 1024
#define NSSP 1088          // padded stride for g_kv (padding row stays zero)
#define PREF 63            // tags + visual prefix length

// Scratch (device globals: allocation-free per harness rules)
__device__ float g_q[(size_t)BB * HH * SS * DHH];       // Q, pre-scaled+tf32
__device__ float g_a[(size_t)BB * SS * NXX];            // attn out (tf32-rounded)
__device__ float g_wt[(size_t)6144 * 1024];             // tf32 weights
__device__ float g_xc[(size_t)BB * SS * NXX];           // tf32 x
__device__ float g_vc[(size_t)BB * NVV * 1024];         // tf32 visual
__device__ float g_kv[(size_t)BB * 2 * HH * NSSP * DHH];// tf32 K/V, padded stride
#define OFF_WT_ATTN 0
#define OFF_WT_VIS  (3072 * 1024)
#define OFF_WT_PROJ (5120 * 1024)

// ---------------------------------------------------------------------------
__device__ __forceinline__ uint32_t f2tf32(float x) {
    uint32_t y;
    asm("cvt.rna.tf32.f32 %0, %1;" : "=r"(y) : "f"(x));
    return y;
}

__device__ __forceinline__ void mma_tf32(float* c, const uint32_t* a, const uint32_t* b) {
    asm volatile(
        "mma.sync.aligned.m16n8k8.row.col.f32.tf32.tf32.f32 "
        "{%0,%1,%2,%3}, {%4,%5,%6,%7}, {%8,%9}, {%0,%1,%2,%3};\n"
        : "+f"(c[0]), "+f"(c[1]), "+f"(c[2]), "+f"(c[3])
        : "r"(a[0]), "r"(a[1]), "r"(a[2]), "r"(a[3]), "r"(b[0]), "r"(b[1]));
}

__device__ __forceinline__ uint32_t smem_u32(const void* p) {
    uint32_t a;
    asm("{ .reg .u64 t; cvta.to.shared.u64 t, %1; cvt.u32.u64 %0, t; }"
        : "=r"(a) : "l"(p));
    return a;
}

// ---------------------------------------------------------------------------
// Elementwise tf32 rounding prep
// ---------------------------------------------------------------------------
__global__ __launch_bounds__(256) void cvt_tf32_kernel(
    const float* __restrict__ in, float* __restrict__ out, int n)
{
    int i = (blockIdx.x * 256 + threadIdx.x) * 4;
    if (i < n) {
        float4 v = *(const float4*)(in + i);
        uint4 p;
        p.x = f2tf32(v.x); p.y = f2tf32(v.y);
        p.z = f2tf32(v.z); p.w = f2tf32(v.w);
        *(uint4*)(out + i) = p;
    }
}

// ---------------------------------------------------------------------------
// scatter helper: writes present (exact) plus tf32-rounded copies for attention
// ---------------------------------------------------------------------------
template <int MODE>
__device__ __forceinline__ void scatter(int r, int c, float val,
                                        float* __restrict__ present,
                                        float* __restrict__ outp)
{
    if (MODE == 0) {
        int b = r >> 10, s = r & 1023;
        int sect = c >> 10, cc = c & 1023;
        int h = cc >> 6, d = cc & 63;
        if (sect == 0) {
            g_q[((((size_t)b * HH + h) * SS + s) << 6) + d] =
                __uint_as_float(f2tf32(val * 0.125f));
        } else {
            present[(((((size_t)b * 2 + (sect - 1)) * HH + h) * NSS +
                      (PREF + s)) << 6) + d] = val;
            g_kv[(((((size_t)b * 2 + (sect - 1)) * HH + h) * NSSP +
                   (PREF + s)) << 6) + d] = __uint_as_float(f2tf32(val));
        }
    } else if (MODE == 1) {
        int b = r / NVV, p = r % NVV;
        int sect = c >> 10, cc = c & 1023;
        int h = cc >> 6, d = cc & 63;
        present[(((((size_t)b * 2 + sect) * HH + h) * NSS + (NTT + p)) << 6) + d] = val;
        g_kv[(((((size_t)b * 2 + sect) * HH + h) * NSSP + (NTT + p)) << 6) + d] =
            __uint_as_float(f2tf32(val));
    } else if (MODE == 2) {
        int b = r / NTT, p = r % NTT;
        int sect = c >> 10, cc = c & 1023;
        int h = cc >> 6, d = cc & 63;
        present[(((((size_t)b * 2 + sect) * HH + h) * NSS + p) << 6) + d] = val;
        g_kv[(((((size_t)b * 2 + sect) * HH + h) * NSSP + p) << 6) + d] =
            __uint_as_float(f2tf32(val));
    } else {
        outp[(size_t)r * NXX + c] = val;
    }
}

// ---------------------------------------------------------------------------
// tf32 mma GEMM with cp.async 2-stage pipeline (champion version, unchanged).
// ---------------------------------------------------------------------------
template <int MODE>
__global__ __launch_bounds__(256, 2) void mma_gemm(
    const float* __restrict__ A, const float* __restrict__ W,
    const float* __restrict__ bias, float* __restrict__ present,
    float* __restrict__ outp, int M, int N, int K)
{
    extern __shared__ uint32_t sm[];
    const int bm = blockIdx.y, bn = blockIdx.x;
    const int tid = threadIdx.x;
    const int warp = tid >> 5, lane = tid & 31;
    const int wm = warp >> 1, wn = warp & 1;
    const int lq = lane >> 2, lr = lane & 3;

    const uint32_t sbase = smem_u32(sm);

    auto issue = [&](int s, int kt) {
        uint32_t abase = sbase + s * 35840;
        uint32_t bbase = abase + 18432;
#pragma unroll
        for (int i = 0; i < 4; i++) {
            int flat = tid + 256 * i;
            int m = flat >> 3, kc = flat & 7;
            int gm = bm * 128 + m;
            const float* src = A + (size_t)gm * K + kt + kc * 4;
            uint32_t dst = abase + m * 144 + kc * 16;
            int sz = (gm < M) ? 16 : 0;
            asm volatile("cp.async.ca.shared.global [%0], [%1], 16, %2;"
                         :: "r"(dst), "l"(src), "r"(sz));
        }
#pragma unroll
        for (int i = 0; i < 4; i++) {
            int flat = tid + 256 * i;
            int k = flat >> 5, nc = flat & 31;
            const float* src = W + (size_t)(kt + k) * N + bn * 128 + nc * 4;
            uint32_t dst = bbase + k * 544 + nc * 16;
            asm volatile("cp.async.ca.shared.global [%0], [%1], 16;"
                         :: "r"(dst), "l"(src));
        }
        asm volatile("cp.async.commit_group;");
    };

    float acc[2][8][4];
#pragma unroll
    for (int mt = 0; mt < 2; mt++)
#pragma unroll
        for (int nt = 0; nt < 8; nt++)
#pragma unroll
            for (int u = 0; u < 4; u++) acc[mt][nt][u] = 0.f;

    const int NC = K >> 5;
    issue(0, 0);
    if (NC > 1) issue(1, 32);
    else asm volatile("cp.async.commit_group;");

    for (int c = 0; c < NC; c++) {
        const int s = c & 1;
        asm volatile("cp.async.wait_group 1;" ::: "memory");
        __syncthreads();

        const uint32_t* Asw = sm + s * 8960;
        const uint32_t* Bsw = Asw + 4608;

#pragma unroll
        for (int g = 0; g < 4; g++) {
            uint32_t af[2][4];
#pragma unroll
            for (int mt = 0; mt < 2; mt++) {
                int r = wm * 32 + mt * 16 + lq;
                af[mt][0] = Asw[r * 36 + g * 8 + lr];
                af[mt][1] = Asw[(r + 8) * 36 + g * 8 + lr];
                af[mt][2] = Asw[r * 36 + g * 8 + lr + 4];
                af[mt][3] = Asw[(r + 8) * 36 + g * 8 + lr + 4];
            }
            uint32_t bf[8][2];
#pragma unroll
            for (int nt = 0; nt < 8; nt++) {
                int n = wn * 64 + nt * 8 + lq;
                bf[nt][0] = Bsw[(g * 8 + lr) * 136 + n];
                bf[nt][1] = Bsw[(g * 8 + lr + 4) * 136 + n];
            }
#pragma unroll
            for (int mt = 0; mt < 2; mt++)
#pragma unroll
                for (int nt = 0; nt < 8; nt++)
                    mma_tf32(acc[mt][nt], af[mt], bf[nt]);
        }
        __syncthreads();
        if (c + 2 < NC) issue(s, (c + 2) << 5);
        else asm volatile("cp.async.commit_group;");
    }

#pragma unroll
    for (int mt = 0; mt < 2; mt++) {
        int r0 = bm * 128 + wm * 32 + mt * 16 + lq;
#pragma unroll
        for (int nt = 0; nt < 8; nt++) {
            int c0 = bn * 128 + wn * 64 + nt * 8 + (lr << 1);
            float bz0 = bias[c0], bz1 = bias[c0 + 1];
            if (r0 < M) {
                scatter<MODE>(r0, c0,     acc[mt][nt][0] + bz0, present, outp);
                scatter<MODE>(r0, c0 + 1, acc[mt][nt][1] + bz1, present, outp);
            }
            if (r0 + 8 < M) {
                scatter<MODE>(r0 + 8, c0,     acc[mt][nt][2] + bz0, present, outp);
                scatter<MODE>(r0 + 8, c0 + 1, acc[mt][nt][3] + bz1, present, outp);
            }
        }
    }
}

// ---------------------------------------------------------------------------
// FFMA SGEMM for tags (K=400, full fp32)
// ---------------------------------------------------------------------------
template <int MODE>
__global__ __launch_bounds__(256) void gemm_kernel(
    const float* __restrict__ A, const float* __restrict__ W,
    const float* __restrict__ bias, float* __restrict__ present,
    float* __restrict__ outp, int M, int N, int K)
{
    __shared__ float As[8][128];
    __shared__ float Bs[8][128];

    const int bm = blockIdx.y, bn = blockIdx.x;
    const int tid = threadIdx.x;
    const int ty = tid >> 4, tx = tid & 15;

    const int arow = tid >> 1;
    const int acol = (tid & 1) << 2;
    const int wrow = tid >> 5;
    const int wcol = (tid & 31) << 2;

    const int gArow = bm * 128 + arow;
    const float* aptr = A + (size_t)gArow * K + acol;
    const float* wptr = W + (size_t)wrow * N + bn * 128 + wcol;

    float acc[8][8];
#pragma unroll
    for (int i = 0; i < 8; i++)
#pragma unroll
        for (int j = 0; j < 8; j++) acc[i][j] = 0.f;

    for (int k0 = 0; k0 < K; k0 += 8) {
        float4 av = make_float4(0.f, 0.f, 0.f, 0.f);
        if (gArow < M) av = *(const float4*)(aptr + k0);
        As[acol + 0][arow] = av.x;
        As[acol + 1][arow] = av.y;
        As[acol + 2][arow] = av.z;
        As[acol + 3][arow] = av.w;
        *(float4*)&Bs[wrow][wcol] = *(const float4*)(wptr + (size_t)k0 * N);
        __syncthreads();
#pragma unroll
        for (int kk = 0; kk < 8; kk++) {
            float4 a0 = *(const float4*)&As[kk][ty * 8];
            float4 a1 = *(const float4*)&As[kk][ty * 8 + 4];
            float4 b0 = *(const float4*)&Bs[kk][tx * 8];
            float4 b1 = *(const float4*)&Bs[kk][tx * 8 + 4];
            float ar[8] = {a0.x, a0.y, a0.z, a0.w, a1.x, a1.y, a1.z, a1.w};
            float br[8] = {b0.x, b0.y, b0.z, b0.w, b1.x, b1.y, b1.z, b1.w};
#pragma unroll
            for (int i = 0; i < 8; i++)
#pragma unroll
                for (int j = 0; j < 8; j++) acc[i][j] += ar[i] * br[j];
        }
        __syncthreads();
    }

#pragma unroll
    for (int i = 0; i < 8; i++) {
        int r = bm * 128 + ty * 8 + i;
        if (r >= M) continue;
#pragma unroll
        for (int j = 0; j < 8; j++) {
            int c = bn * 128 + tx * 8 + j;
            scatter<MODE>(r, c, acc[i][j] + bias[c], present, outp);
        }
    }
}

// ---------------------------------------------------------------------------
// Flash attention v6: 64-q tile, 128 threads, tf32 mma.
// Q fragments in registers. SINGLE K/V buffer (exposed refill) to shrink smem
// to 37888 B -> 4 CTAs/SM (16 warps) via __launch_bounds__(128,4).
// K stride 76 (frag banks 12*lq+lr distinct), V stride 72 (8*lr+lq distinct).
// ---------------------------------------------------------------------------
#define KST 76
#define VST 72
#define KTW (64 * KST)            // 4864 words
#define VTW (64 * VST)            // 4608 words
#define PAIRW (KTW + VTW)         // 9472 words total

__global__ __launch_bounds__(128, 4) void attn_mma()
{
    extern __shared__ uint32_t sm[];
    // layout: K | V

    const int qt = (int)(gridDim.x - 1) - blockIdx.x;   // heavy blocks first
    const int h = blockIdx.y, b = blockIdx.z;
    const int tid = threadIdx.x;
    const int warp = tid >> 5, lane = tid & 31;
    const int lq = lane >> 2, lr = lane & 3;

    const float* qsrc  = g_q  + ((((size_t)b * HH + h) * SS + qt * 64) << 6);
    const char*  kbase = (const char*)(g_kv + (((((size_t)b * 2 + 0) * HH + h) * NSSP) << 6));
    const char*  vbase = (const char*)(g_kv + (((((size_t)b * 2 + 1) * HH + h) * NSSP) << 6));

    const uint32_t sbase = smem_u32(sm);
    const uint32_t sK = sbase, sV = sbase + KTW * 4;
    const int tmax = qt + 1;

    // ---- stage Q through the K buffer, pull fragments into registers ----
#pragma unroll
    for (int i = 0; i < 8; i++) {
        int c = tid + 128 * i;
        int row = c >> 4, q16 = (c & 15) << 4;
        asm volatile("cp.async.ca.shared.global [%0], [%1], 16;"
                     :: "r"(sK + row * (KST * 4) + q16),
                        "l"((const char*)qsrc + (row << 8) + q16));
    }
    asm volatile("cp.async.commit_group;");
    asm volatile("cp.async.wait_group 0;" ::: "memory");
    __syncthreads();

    uint32_t Qf[8][4];
#pragma unroll
    for (int k0 = 0; k0 < 8; k0++) {
        const int rb = (warp * 16 + lq) * KST + k0 * 8;
        Qf[k0][0] = sm[rb + lr];
        Qf[k0][1] = sm[rb + 8 * KST + lr];
        Qf[k0][2] = sm[rb + lr + 4];
        Qf[k0][3] = sm[rb + 8 * KST + lr + 4];
    }
    __syncthreads();   // Q reads done before K tile 0 overwrites buffer

    // ---- K/V tile fill (single buffer) ----
    auto issue_tile = [&](int t) {
        const char* ks = kbase + ((size_t)t << 14);
        const char* vs = vbase + ((size_t)t << 14);
#pragma unroll
        for (int i = 0; i < 8; i++) {
            int c = tid + 128 * i;
            int row = c >> 4, q16 = (c & 15) << 4;
            int goff = (row << 8) + q16;
            asm volatile("cp.async.ca.shared.global [%0], [%1], 16;"
                         :: "r"(sK + row * (KST * 4) + q16), "l"(ks + goff));
            asm volatile("cp.async.ca.shared.global [%0], [%1], 16;"
                         :: "r"(sV + row * (VST * 4) + q16), "l"(vs + goff));
        }
        asm volatile("cp.async.commit_group;");
    };

    issue_tile(0);
    asm volatile("cp.async.wait_group 0;" ::: "memory");
    __syncthreads();

    float Oa[8][4];
#pragma unroll
    for (int nd = 0; nd < 8; nd++)
#pragma unroll
        for (int u = 0; u < 4; u++) Oa[nd][u] = 0.f;
    float m0 = -1e30f, m1 = -1e30f, l0 = 0.f, l1 = 0.f;

    const int warp_r0 = qt * 64 + warp * 16;
    const int r0g = warp_r0 + lq;

    float Sa[8][4];
    const uint32_t* Ks = sm;
    const uint32_t* Vs = sm + KTW;

    for (int t = 0; t <= tmax; t++) {
        // ---- S = Q K^T ----
#pragma unroll
        for (int nt = 0; nt < 8; nt++)
#pragma unroll
            for (int u = 0; u < 4; u++) Sa[nt][u] = 0.f;

#pragma unroll
        for (int k0 = 0; k0 < 8; k0++) {
#pragma unroll
            for (int nt = 0; nt < 8; nt++) {
                uint32_t bf[2];
                const int kb = (nt * 8 + lq) * KST + k0 * 8 + lr;
                bf[0] = Ks[kb];
                bf[1] = Ks[kb + 4];
                mma_tf32(Sa[nt], Qf[k0], bf);
            }
        }

        // boundary mask (causal diag + NSS edge) only when the tile can clip
        if (t * 64 + 63 > warp_r0 + PREF) {
#pragma unroll
            for (int nt = 0; nt < 8; nt++) {
                int j0 = t * 64 + nt * 8 + (lr << 1);
                if (j0     > r0g + PREF     || j0     >= NSS) Sa[nt][0] = -1e30f;
                if (j0 + 1 > r0g + PREF     || j0 + 1 >= NSS) Sa[nt][1] = -1e30f;
                if (j0     > r0g + 8 + PREF || j0     >= NSS) Sa[nt][2] = -1e30f;
                if (j0 + 1 > r0g + 8 + PREF || j0 + 1 >= NSS) Sa[nt][3] = -1e30f;
            }
        }

        // ---- online softmax (rows lq, lq+8) ----
        float mx0 = -1e30f, mx1 = -1e30f;
#pragma unroll
        for (int nt = 0; nt < 8; nt++) {
            mx0 = fmaxf(mx0, fmaxf(Sa[nt][0], Sa[nt][1]));
            mx1 = fmaxf(mx1, fmaxf(Sa[nt][2], Sa[nt][3]));
        }
        mx0 = fmaxf(mx0, __shfl_xor_sync(0xffffffffu, mx0, 1));
        mx0 = fmaxf(mx0, __shfl_xor_sync(0xffffffffu, mx0, 2));
        mx1 = fmaxf(mx1, __shfl_xor_sync(0xffffffffu, mx1, 1));
        mx1 = fmaxf(mx1, __shfl_xor_sync(0xffffffffu, mx1, 2));
        float mn0 = fmaxf(m0, mx0), mn1 = fmaxf(m1, mx1);
        float cr0 = __expf(m0 - mn0), cr1 = __expf(m1 - mn1);
        float s0 = 0.f, s1 = 0.f;
#pragma unroll
        for (int nt = 0; nt < 8; nt++) {
            float e0 = __expf(Sa[nt][0] - mn0); Sa[nt][0] = e0; s0 += e0;
            float e1 = __expf(Sa[nt][1] - mn0); Sa[nt][1] = e1; s0 += e1;
            float e2 = __expf(Sa[nt][2] - mn1); Sa[nt][2] = e2; s1 += e2;
            float e3 = __expf(Sa[nt][3] - mn1); Sa[nt][3] = e3; s1 += e3;
        }
        s0 += __shfl_xor_sync(0xffffffffu, s0, 1);
        s0 += __shfl_xor_sync(0xffffffffu, s0, 2);
        s1 += __shfl_xor_sync(0xffffffffu, s1, 1);
        s1 += __shfl_xor_sync(0xffffffffu, s1, 2);
        l0 = l0 * cr0 + s0; l1 = l1 * cr1 + s1;
        m0 = mn0; m1 = mn1;
#pragma unroll
        for (int nd = 0; nd < 8; nd++) {
            Oa[nd][0] *= cr0; Oa[nd][1] *= cr0;
            Oa[nd][2] *= cr1; Oa[nd][3] *= cr1;
        }

        // ---- O += P V ----
        const int sA = (lane & ~3) + (lr >> 1);
        const int sB = sA + 2;
        const bool odd = lr & 1;
#pragma unroll
        for (int kt = 0; kt < 8; kt++) {
            float p0 = __shfl_sync(0xffffffffu, Sa[kt][0], sA);
            float p1 = __shfl_sync(0xffffffffu, Sa[kt][1], sA);
            float p2 = __shfl_sync(0xffffffffu, Sa[kt][2], sA);
            float p3 = __shfl_sync(0xffffffffu, Sa[kt][3], sA);
            float q0 = __shfl_sync(0xffffffffu, Sa[kt][0], sB);
            float q1 = __shfl_sync(0xffffffffu, Sa[kt][1], sB);
            float q2 = __shfl_sync(0xffffffffu, Sa[kt][2], sB);
            float q3 = __shfl_sync(0xffffffffu, Sa[kt][3], sB);
            uint32_t a[4];
            a[0] = f2tf32(odd ? p1 : p0);
            a[1] = f2tf32(odd ? p3 : p2);
            a[2] = f2tf32(odd ? q1 : q0);
            a[3] = f2tf32(odd ? q3 : q2);
#pragma unroll
            for (int nd = 0; nd < 8; nd++) {
                uint32_t bf[2];
                const int vb = (kt * 8 + lr) * VST + nd * 8 + lq;
                bf[0] = Vs[vb];
                bf[1] = Vs[vb + 4 * VST];
                mma_tf32(Oa[nd], a, bf);
            }
        }

        // ---- refill K/V for t+1 (exposed; hidden by other CTAs' compute) ----
        if (t < tmax) {
            __syncthreads();   // all warps done reading K/V
            issue_tile(t + 1);
            asm volatile("cp.async.wait_group 0;" ::: "memory");
            __syncthreads();   // copies visible to all warps
        }
    }

    // finalize + write merged-head layout, tf32-rounded for the proj GEMM
    float inv0 = 1.f / l0, inv1 = 1.f / l1;
    float* ab = g_a + ((size_t)b * SS + qt * 64 + warp * 16) * NXX + h * 64;
#pragma unroll
    for (int nd = 0; nd < 8; nd++) {
        uint2 lo = make_uint2(f2tf32(Oa[nd][0] * inv0), f2tf32(Oa[nd][1] * inv0));
        uint2 hi = make_uint2(f2tf32(Oa[nd][2] * inv1), f2tf32(Oa[nd][3] * inv1));
        *(uint2*)&ab[(size_t)lq * NXX + nd * 8 + (lr << 1)] = lo;
        *(uint2*)&ab[(size_t)(lq + 8) * NXX + nd * 8 + (lr << 1)] = hi;
    }
}

// ---------------------------------------------------------------------------
extern "C" void kernel_launch(void* const* d_in, const int* in_sizes, int n_in,
                              void* d_out, int out_size)
{
    const float* x      = (const float*)d_in[0];
    const float* vis    = (const float*)d_in[1];
    const float* tags   = (const float*)d_in[2];
    const float* W_attn = (const float*)d_in[3];
    const float* b_attn = (const float*)d_in[4];
    const float* W_vis  = (const float*)d_in[5];
    const float* b_vis  = (const float*)d_in[6];
    const float* W_tags = (const float*)d_in[7];
    const float* b_tags = (const float*)d_in[8];
    const float* W_proj = (const float*)d_in[9];
    const float* b_proj = (const float*)d_in[10];

    float* out = (float*)d_out;
    float* present = out + (size_t)BB * SS * NXX;   // a first, then present

    static float *wt_base = nullptr, *xc = nullptr, *vc = nullptr, *ga = nullptr;
    const int DSM = 71680;              // 2 stages x 35840 (champion GEMM)
    const int DSM_ATTN = PAIRW * 4;     // 37888 -> 4 CTAs/SM
    if (!wt_base) {
        cudaGetSymbolAddress((void**)&wt_base, g_wt);
        cudaGetSymbolAddress((void**)&xc, g_xc);
        cudaGetSymbolAddress((void**)&vc, g_vc);
        cudaGetSymbolAddress((void**)&ga, g_a);
        cudaFuncSetAttribute(mma_gemm<0>, cudaFuncAttributeMaxDynamicSharedMemorySize, DSM);
        cudaFuncSetAttribute(mma_gemm<1>, cudaFuncAttributeMaxDynamicSharedMemorySize, DSM);
        cudaFuncSetAttribute(mma_gemm<3>, cudaFuncAttributeMaxDynamicSharedMemorySize, DSM);
        cudaFuncSetAttribute(attn_mma, cudaFuncAttributeMaxDynamicSharedMemorySize, DSM_ATTN);
    }
    float* wt_attn = wt_base + OFF_WT_ATTN;
    float* wt_vis  = wt_base + OFF_WT_VIS;
    float* wt_proj = wt_base + OFF_WT_PROJ;

    // Pre-round weights and activations to tf32
    cvt_tf32_kernel<<<3072, 256>>>(W_attn, wt_attn, 3072 * 1024);
    cvt_tf32_kernel<<<2048, 256>>>(W_vis,  wt_vis,  2048 * 1024);
    cvt_tf32_kernel<<<1024, 256>>>(W_proj, wt_proj, 1024 * 1024);
    cvt_tf32_kernel<<<8192, 256>>>(x,   xc, BB * SS * NXX);
    cvt_tf32_kernel<<<392,  256>>>(vis, vc, BB * NVV * 1024);

    // QKV: [8192,1024] @ [1024,3072]
    mma_gemm<0><<<dim3(3072 / 128, 8192 / 128), 256, DSM>>>(
        xc, wt_attn, b_attn, present, nullptr, BB * SS, 3 * NXX, NXX);
    // visual: [392,1024] @ [1024,2048]
    mma_gemm<1><<<dim3(2048 / 128, 4), 256, DSM>>>(
        vc, wt_vis, b_vis, present, nullptr, BB * NVV, 2 * NXX, 1024);
    // tags: [112,400] @ [400,2048]  (FFMA)
    gemm_kernel<2><<<dim3(2048 / 128, 1), 256>>>(
        tags, W_tags, b_tags, present, nullptr, BB * NTT, 2 * NXX, 400);
    // attention (tf32 mma, Q-in-regs, single-buffer K/V, 4 CTAs/SM)
    attn_mma<<<dim3(SS / 64, HH, BB), 128, DSM_ATTN>>>();
    // proj: [8192,1024] @ [1024,1024]
    mma_gemm<3><<<dim3(1024 / 128, 8192 / 128), 256, DSM>>>(
        ga, wt_proj, b_proj, nullptr, out, BB * SS, NXX, NXX);
}

// round 14
// speedup vs baseline: 1.0159x; 1.0159x over previous
#include <cuda_runtime.h>
#include <cstdint>

// Problem constants
#define BB   8
#define SS   1024
#define NXX  1024
#define HH   16
#define DHH  64
#define NVV  49
#define NTT  14
#define NSS  1087          // 14 + 49 + 1024
#define NSSP 1088          // padded stride for g_kv (padding row stays zero)
#define PREF 63            // tags + visual prefix length

// Scratch (device globals: allocation-free per harness rules)
__device__ float g_q[(size_t)BB * HH * SS * DHH];       // Q, pre-scaled+tf32
__device__ float g_a[(size_t)BB * SS * NXX];            // attn out (tf32-rounded)
__device__ float g_wt[(size_t)6144 * 1024];             // tf32 weights
__device__ float g_xc[(size_t)BB * SS * NXX];           // tf32 x
__device__ float g_vc[(size_t)BB * NVV * 1024];         // tf32 visual
__device__ float g_kv[(size_t)BB * 2 * HH * NSSP * DHH];// tf32 K/V, padded stride
#define OFF_WT_ATTN 0
#define OFF_WT_VIS  (3072 * 1024)
#define OFF_WT_PROJ (5120 * 1024)

// ---------------------------------------------------------------------------
__device__ __forceinline__ uint32_t f2tf32(float x) {
    uint32_t y;
    asm("cvt.rna.tf32.f32 %0, %1;" : "=r"(y) : "f"(x));
    return y;
}

__device__ __forceinline__ void mma_tf32(float* c, const uint32_t* a, const uint32_t* b) {
    asm volatile(
        "mma.sync.aligned.m16n8k8.row.col.f32.tf32.tf32.f32 "
        "{%0,%1,%2,%3}, {%4,%5,%6,%7}, {%8,%9}, {%0,%1,%2,%3};\n"
        : "+f"(c[0]), "+f"(c[1]), "+f"(c[2]), "+f"(c[3])
        : "r"(a[0]), "r"(a[1]), "r"(a[2]), "r"(a[3]), "r"(b[0]), "r"(b[1]));
}

__device__ __forceinline__ uint32_t smem_u32(const void* p) {
    uint32_t a;
    asm("{ .reg .u64 t; cvta.to.shared.u64 t, %1; cvt.u32.u64 %0, t; }"
        : "=r"(a) : "l"(p));
    return a;
}

// ---------------------------------------------------------------------------
// Merged tf32 rounding prep: one launch, 5 regions (block-index dispatch).
// Each block handles 1024 elements (256 threads x float4).
// ---------------------------------------------------------------------------
__global__ __launch_bounds__(256) void cvt_tf32_multi(
    const float* s0, float* d0, int b0,   // W_attn  (3072 blocks)
    const float* s1, float* d1, int b1,   // W_vis   (2048)
    const float* s2, float* d2, int b2,   // W_proj  (1024)
    const float* s3, float* d3, int b3,   // x       (8192)
    const float* s4, float* d4, int b4)   // vis     (392)
{
    int blk = blockIdx.x;
    const float* src; float* dst;
    if (blk < b0)                { src = s0; dst = d0; }
    else if ((blk -= b0) < b1)   { src = s1; dst = d1; }
    else if ((blk -= b1) < b2)   { src = s2; dst = d2; }
    else if ((blk -= b2) < b3)   { src = s3; dst = d3; }
    else { blk -= b3;              src = s4; dst = d4; }
    size_t i = ((size_t)blk * 256 + threadIdx.x) * 4;
    float4 v = *(const float4*)(src + i);
    uint4 p;
    p.x = f2tf32(v.x); p.y = f2tf32(v.y);
    p.z = f2tf32(v.z); p.w = f2tf32(v.w);
    *(uint4*)(dst + i) = p;
}

// ---------------------------------------------------------------------------
// scatter helper: writes present (exact) plus tf32-rounded copies for attention
// ---------------------------------------------------------------------------
template <int MODE>
__device__ __forceinline__ void scatter(int r, int c, float val,
                                        float* __restrict__ present,
                                        float* __restrict__ outp)
{
    if (MODE == 0) {
        int b = r >> 10, s = r & 1023;
        int sect = c >> 10, cc = c & 1023;
        int h = cc >> 6, d = cc & 63;
        if (sect == 0) {
            g_q[((((size_t)b * HH + h) * SS + s) << 6) + d] =
                __uint_as_float(f2tf32(val * 0.125f));
        } else {
            present[(((((size_t)b * 2 + (sect - 1)) * HH + h) * NSS +
                      (PREF + s)) << 6) + d] = val;
            g_kv[(((((size_t)b * 2 + (sect - 1)) * HH + h) * NSSP +
                   (PREF + s)) << 6) + d] = __uint_as_float(f2tf32(val));
        }
    } else if (MODE == 1) {
        int b = r / NVV, p = r % NVV;
        int sect = c >> 10, cc = c & 1023;
        int h = cc >> 6, d = cc & 63;
        present[(((((size_t)b * 2 + sect) * HH + h) * NSS + (NTT + p)) << 6) + d] = val;
        g_kv[(((((size_t)b * 2 + sect) * HH + h) * NSSP + (NTT + p)) << 6) + d] =
            __uint_as_float(f2tf32(val));
    } else if (MODE == 2) {
        int b = r / NTT, p = r % NTT;
        int sect = c >> 10, cc = c & 1023;
        int h = cc >> 6, d = cc & 63;
        present[(((((size_t)b * 2 + sect) * HH + h) * NSS + p) << 6) + d] = val;
        g_kv[(((((size_t)b * 2 + sect) * HH + h) * NSSP + p) << 6) + d] =
            __uint_as_float(f2tf32(val));
    } else {
        outp[(size_t)r * NXX + c] = val;
    }
}

// ---------------------------------------------------------------------------
// tf32 mma GEMM with cp.async 2-stage pipeline (champion version, unchanged).
// ---------------------------------------------------------------------------
template <int MODE>
__global__ __launch_bounds__(256, 2) void mma_gemm(
    const float* __restrict__ A, const float* __restrict__ W,
    const float* __restrict__ bias, float* __restrict__ present,
    float* __restrict__ outp, int M, int N, int K)
{
    extern __shared__ uint32_t sm[];
    const int bm = blockIdx.y, bn = blockIdx.x;
    const int tid = threadIdx.x;
    const int warp = tid >> 5, lane = tid & 31;
    const int wm = warp >> 1, wn = warp & 1;
    const int lq = lane >> 2, lr = lane & 3;

    const uint32_t sbase = smem_u32(sm);

    auto issue = [&](int s, int kt) {
        uint32_t abase = sbase + s * 35840;
        uint32_t bbase = abase + 18432;
#pragma unroll
        for (int i = 0; i < 4; i++) {
            int flat = tid + 256 * i;
            int m = flat >> 3, kc = flat & 7;
            int gm = bm * 128 + m;
            const float* src = A + (size_t)gm * K + kt + kc * 4;
            uint32_t dst = abase + m * 144 + kc * 16;
            int sz = (gm < M) ? 16 : 0;
            asm volatile("cp.async.ca.shared.global [%0], [%1], 16, %2;"
                         :: "r"(dst), "l"(src), "r"(sz));
        }
#pragma unroll
        for (int i = 0; i < 4; i++) {
            int flat = tid + 256 * i;
            int k = flat >> 5, nc = flat & 31;
            const float* src = W + (size_t)(kt + k) * N + bn * 128 + nc * 4;
            uint32_t dst = bbase + k * 544 + nc * 16;
            asm volatile("cp.async.ca.shared.global [%0], [%1], 16;"
                         :: "r"(dst), "l"(src));
        }
        asm volatile("cp.async.commit_group;");
    };

    float acc[2][8][4];
#pragma unroll
    for (int mt = 0; mt < 2; mt++)
#pragma unroll
        for (int nt = 0; nt < 8; nt++)
#pragma unroll
            for (int u = 0; u < 4; u++) acc[mt][nt][u] = 0.f;

    const int NC = K >> 5;
    issue(0, 0);
    if (NC > 1) issue(1, 32);
    else asm volatile("cp.async.commit_group;");

    for (int c = 0; c < NC; c++) {
        const int s = c & 1;
        asm volatile("cp.async.wait_group 1;" ::: "memory");
        __syncthreads();

        const uint32_t* Asw = sm + s * 8960;
        const uint32_t* Bsw = Asw + 4608;

#pragma unroll
        for (int g = 0; g < 4; g++) {
            uint32_t af[2][4];
#pragma unroll
            for (int mt = 0; mt < 2; mt++) {
                int r = wm * 32 + mt * 16 + lq;
                af[mt][0] = Asw[r * 36 + g * 8 + lr];
                af[mt][1] = Asw[(r + 8) * 36 + g * 8 + lr];
                af[mt][2] = Asw[r * 36 + g * 8 + lr + 4];
                af[mt][3] = Asw[(r + 8) * 36 + g * 8 + lr + 4];
            }
            uint32_t bf[8][2];
#pragma unroll
            for (int nt = 0; nt < 8; nt++) {
                int n = wn * 64 + nt * 8 + lq;
                bf[nt][0] = Bsw[(g * 8 + lr) * 136 + n];
                bf[nt][1] = Bsw[(g * 8 + lr + 4) * 136 + n];
            }
#pragma unroll
            for (int mt = 0; mt < 2; mt++)
#pragma unroll
                for (int nt = 0; nt < 8; nt++)
                    mma_tf32(acc[mt][nt], af[mt], bf[nt]);
        }
        __syncthreads();
        if (c + 2 < NC) issue(s, (c + 2) << 5);
        else asm volatile("cp.async.commit_group;");
    }

#pragma unroll
    for (int mt = 0; mt < 2; mt++) {
        int r0 = bm * 128 + wm * 32 + mt * 16 + lq;
#pragma unroll
        for (int nt = 0; nt < 8; nt++) {
            int c0 = bn * 128 + wn * 64 + nt * 8 + (lr << 1);
            float bz0 = bias[c0], bz1 = bias[c0 + 1];
            if (r0 < M) {
                scatter<MODE>(r0, c0,     acc[mt][nt][0] + bz0, present, outp);
                scatter<MODE>(r0, c0 + 1, acc[mt][nt][1] + bz1, present, outp);
            }
            if (r0 + 8 < M) {
                scatter<MODE>(r0 + 8, c0,     acc[mt][nt][2] + bz0, present, outp);
                scatter<MODE>(r0 + 8, c0 + 1, acc[mt][nt][3] + bz1, present, outp);
            }
        }
    }
}

// ---------------------------------------------------------------------------
// FFMA SGEMM for tags (K=400, full fp32)
// ---------------------------------------------------------------------------
template <int MODE>
__global__ __launch_bounds__(256) void gemm_kernel(
    const float* __restrict__ A, const float* __restrict__ W,
    const float* __restrict__ bias, float* __restrict__ present,
    float* __restrict__ outp, int M, int N, int K)
{
    __shared__ float As[8][128];
    __shared__ float Bs[8][128];

    const int bm = blockIdx.y, bn = blockIdx.x;
    const int tid = threadIdx.x;
    const int ty = tid >> 4, tx = tid & 15;

    const int arow = tid >> 1;
    const int acol = (tid & 1) << 2;
    const int wrow = tid >> 5;
    const int wcol = (tid & 31) << 2;

    const int gArow = bm * 128 + arow;
    const float* aptr = A + (size_t)gArow * K + acol;
    const float* wptr = W + (size_t)wrow * N + bn * 128 + wcol;

    float acc[8][8];
#pragma unroll
    for (int i = 0; i < 8; i++)
#pragma unroll
        for (int j = 0; j < 8; j++) acc[i][j] = 0.f;

    for (int k0 = 0; k0 < K; k0 += 8) {
        float4 av = make_float4(0.f, 0.f, 0.f, 0.f);
        if (gArow < M) av = *(const float4*)(aptr + k0);
        As[acol + 0][arow] = av.x;
        As[acol + 1][arow] = av.y;
        As[acol + 2][arow] = av.z;
        As[acol + 3][arow] = av.w;
        *(float4*)&Bs[wrow][wcol] = *(const float4*)(wptr + (size_t)k0 * N);
        __syncthreads();
#pragma unroll
        for (int kk = 0; kk < 8; kk++) {
            float4 a0 = *(const float4*)&As[kk][ty * 8];
            float4 a1 = *(const float4*)&As[kk][ty * 8 + 4];
            float4 b0 = *(const float4*)&Bs[kk][tx * 8];
            float4 b1 = *(const float4*)&Bs[kk][tx * 8 + 4];
            float ar[8] = {a0.x, a0.y, a0.z, a0.w, a1.x, a1.y, a1.z, a1.w};
            float br[8] = {b0.x, b0.y, b0.z, b0.w, b1.x, b1.y, b1.z, b1.w};
#pragma unroll
            for (int i = 0; i < 8; i++)
#pragma unroll
                for (int j = 0; j < 8; j++) acc[i][j] += ar[i] * br[j];
        }
        __syncthreads();
    }

#pragma unroll
    for (int i = 0; i < 8; i++) {
        int r = bm * 128 + ty * 8 + i;
        if (r >= M) continue;
#pragma unroll
        for (int j = 0; j < 8; j++) {
            int c = bn * 128 + tx * 8 + j;
            scatter<MODE>(r, c, acc[i][j] + bias[c], present, outp);
        }
    }
}

// ---------------------------------------------------------------------------
// Flash attention v7: round-12 champion with single-barrier pipeline.
// Per phase: wait_group 0 -> bar -> issue(t+1) -> compute(t).
// Q fragments in registers. K stride 76, V stride 72 (conflict-free frags).
// smem: 2 x (K 64x76 + V 64x72) = 75776 B -> 3 CTAs/SM.
// ---------------------------------------------------------------------------
#define KST 76
#define VST 72
#define KTW (64 * KST)            // 4864 words
#define VTW (64 * VST)            // 4608 words
#define PAIRW (KTW + VTW)         // 9472 words per stage

__global__ __launch_bounds__(128, 3) void attn_mma()
{
    extern __shared__ uint32_t sm[];
    // layout: K0 | V0 | K1 | V1

    const int qt = (int)(gridDim.x - 1) - blockIdx.x;   // heavy blocks first
    const int h = blockIdx.y, b = blockIdx.z;
    const int tid = threadIdx.x;
    const int warp = tid >> 5, lane = tid & 31;
    const int lq = lane >> 2, lr = lane & 3;

    const float* qsrc  = g_q  + ((((size_t)b * HH + h) * SS + qt * 64) << 6);
    const char*  kbase = (const char*)(g_kv + (((((size_t)b * 2 + 0) * HH + h) * NSSP) << 6));
    const char*  vbase = (const char*)(g_kv + (((((size_t)b * 2 + 1) * HH + h) * NSSP) << 6));

    const uint32_t sbase = smem_u32(sm);
    const int tmax = qt + 1;

    // ---- stage Q through K0 buffer, pull fragments into registers ----
#pragma unroll
    for (int i = 0; i < 8; i++) {
        int c = tid + 128 * i;
        int row = c >> 4, q16 = (c & 15) << 4;
        asm volatile("cp.async.ca.shared.global [%0], [%1], 16;"
                     :: "r"(sbase + row * (KST * 4) + q16),
                        "l"((const char*)qsrc + (row << 8) + q16));
    }
    asm volatile("cp.async.commit_group;");
    asm volatile("cp.async.wait_group 0;" ::: "memory");
    __syncthreads();

    uint32_t Qf[8][4];
#pragma unroll
    for (int k0 = 0; k0 < 8; k0++) {
        const int rb = (warp * 16 + lq) * KST + k0 * 8;
        Qf[k0][0] = sm[rb + lr];
        Qf[k0][1] = sm[rb + 8 * KST + lr];
        Qf[k0][2] = sm[rb + lr + 4];
        Qf[k0][3] = sm[rb + 8 * KST + lr + 4];
    }
    __syncthreads();   // Q reads done before K0 tile overwrites buffer

    // ---- K/V tile issue ----
    auto issue_tile = [&](int t) {
        const int s = t & 1;
        const uint32_t kd = sbase + s * PAIRW * 4;
        const uint32_t vd = kd + KTW * 4;
        const char* ks = kbase + ((size_t)t << 14);
        const char* vs = vbase + ((size_t)t << 14);
#pragma unroll
        for (int i = 0; i < 8; i++) {
            int c = tid + 128 * i;
            int row = c >> 4, q16 = (c & 15) << 4;
            int goff = (row << 8) + q16;
            asm volatile("cp.async.ca.shared.global [%0], [%1], 16;"
                         :: "r"(kd + row * (KST * 4) + q16), "l"(ks + goff));
            asm volatile("cp.async.ca.shared.global [%0], [%1], 16;"
                         :: "r"(vd + row * (VST * 4) + q16), "l"(vs + goff));
        }
        asm volatile("cp.async.commit_group;");
    };

    issue_tile(0);

    float Oa[8][4];
#pragma unroll
    for (int nd = 0; nd < 8; nd++)
#pragma unroll
        for (int u = 0; u < 4; u++) Oa[nd][u] = 0.f;
    float m0 = -1e30f, m1 = -1e30f, l0 = 0.f, l1 = 0.f;

    const int warp_r0 = qt * 64 + warp * 16;
    const int r0g = warp_r0 + lq;

    float Sa[8][4];

    for (int t = 0; t <= tmax; t++) {
        const int s = t & 1;
        const uint32_t* Ks = sm + s * PAIRW;
        const uint32_t* Vs = Ks + KTW;

        // tile t's group was issued one full phase ago (or just above for t=0)
        asm volatile("cp.async.wait_group 0;" ::: "memory");
        __syncthreads();

        // issue tile t+1 into the other buffer (safe: it was last read in
        // phase t-1 and every warp has passed the barrier above)
        if (t + 1 <= tmax) issue_tile(t + 1);

        // ---- S = Q K^T ----
#pragma unroll
        for (int nt = 0; nt < 8; nt++)
#pragma unroll
            for (int u = 0; u < 4; u++) Sa[nt][u] = 0.f;

#pragma unroll
        for (int k0 = 0; k0 < 8; k0++) {
#pragma unroll
            for (int nt = 0; nt < 8; nt++) {
                uint32_t bf[2];
                const int kb = (nt * 8 + lq) * KST + k0 * 8 + lr;
                bf[0] = Ks[kb];
                bf[1] = Ks[kb + 4];
                mma_tf32(Sa[nt], Qf[k0], bf);
            }
        }

        // boundary mask (causal diag + NSS edge) only when the tile can clip
        if (t * 64 + 63 > warp_r0 + PREF) {
#pragma unroll
            for (int nt = 0; nt < 8; nt++) {
                int j0 = t * 64 + nt * 8 + (lr << 1);
                if (j0     > r0g + PREF     || j0     >= NSS) Sa[nt][0] = -1e30f;
                if (j0 + 1 > r0g + PREF     || j0 + 1 >= NSS) Sa[nt][1] = -1e30f;
                if (j0     > r0g + 8 + PREF || j0     >= NSS) Sa[nt][2] = -1e30f;
                if (j0 + 1 > r0g + 8 + PREF || j0 + 1 >= NSS) Sa[nt][3] = -1e30f;
            }
        }

        // ---- online softmax (rows lq, lq+8) ----
        float mx0 = -1e30f, mx1 = -1e30f;
#pragma unroll
        for (int nt = 0; nt < 8; nt++) {
            mx0 = fmaxf(mx0, fmaxf(Sa[nt][0], Sa[nt][1]));
            mx1 = fmaxf(mx1, fmaxf(Sa[nt][2], Sa[nt][3]));
        }
        mx0 = fmaxf(mx0, __shfl_xor_sync(0xffffffffu, mx0, 1));
        mx0 = fmaxf(mx0, __shfl_xor_sync(0xffffffffu, mx0, 2));
        mx1 = fmaxf(mx1, __shfl_xor_sync(0xffffffffu, mx1, 1));
        mx1 = fmaxf(mx1, __shfl_xor_sync(0xffffffffu, mx1, 2));
        float mn0 = fmaxf(m0, mx0), mn1 = fmaxf(m1, mx1);
        float cr0 = __expf(m0 - mn0), cr1 = __expf(m1 - mn1);
        float s0 = 0.f, s1 = 0.f;
#pragma unroll
        for (int nt = 0; nt < 8; nt++) {
            float e0 = __expf(Sa[nt][0] - mn0); Sa[nt][0] = e0; s0 += e0;
            float e1 = __expf(Sa[nt][1] - mn0); Sa[nt][1] = e1; s0 += e1;
            float e2 = __expf(Sa[nt][2] - mn1); Sa[nt][2] = e2; s1 += e2;
            float e3 = __expf(Sa[nt][3] - mn1); Sa[nt][3] = e3; s1 += e3;
        }
        s0 += __shfl_xor_sync(0xffffffffu, s0, 1);
        s0 += __shfl_xor_sync(0xffffffffu, s0, 2);
        s1 += __shfl_xor_sync(0xffffffffu, s1, 1);
        s1 += __shfl_xor_sync(0xffffffffu, s1, 2);
        l0 = l0 * cr0 + s0; l1 = l1 * cr1 + s1;
        m0 = mn0; m1 = mn1;
#pragma unroll
        for (int nd = 0; nd < 8; nd++) {
            Oa[nd][0] *= cr0; Oa[nd][1] *= cr0;
            Oa[nd][2] *= cr1; Oa[nd][3] *= cr1;
        }

        // ---- O += P V ----
        const int sA = (lane & ~3) + (lr >> 1);
        const int sB = sA + 2;
        const bool odd = lr & 1;
#pragma unroll
        for (int kt = 0; kt < 8; kt++) {
            float p0 = __shfl_sync(0xffffffffu, Sa[kt][0], sA);
            float p1 = __shfl_sync(0xffffffffu, Sa[kt][1], sA);
            float p2 = __shfl_sync(0xffffffffu, Sa[kt][2], sA);
            float p3 = __shfl_sync(0xffffffffu, Sa[kt][3], sA);
            float q0 = __shfl_sync(0xffffffffu, Sa[kt][0], sB);
            float q1 = __shfl_sync(0xffffffffu, Sa[kt][1], sB);
            float q2 = __shfl_sync(0xffffffffu, Sa[kt][2], sB);
            float q3 = __shfl_sync(0xffffffffu, Sa[kt][3], sB);
            uint32_t a[4];
            a[0] = f2tf32(odd ? p1 : p0);
            a[1] = f2tf32(odd ? p3 : p2);
            a[2] = f2tf32(odd ? q1 : q0);
            a[3] = f2tf32(odd ? q3 : q2);
#pragma unroll
            for (int nd = 0; nd < 8; nd++) {
                uint32_t bf[2];
                const int vb = (kt * 8 + lr) * VST + nd * 8 + lq;
                bf[0] = Vs[vb];
                bf[1] = Vs[vb + 4 * VST];
                mma_tf32(Oa[nd], a, bf);
            }
        }
        // no trailing barrier: next phase's wait+bar protects buffer reuse
    }

    // finalize + write merged-head layout, tf32-rounded for the proj GEMM
    float inv0 = 1.f / l0, inv1 = 1.f / l1;
    float* ab = g_a + ((size_t)b * SS + qt * 64 + warp * 16) * NXX + h * 64;
#pragma unroll
    for (int nd = 0; nd < 8; nd++) {
        uint2 lo = make_uint2(f2tf32(Oa[nd][0] * inv0), f2tf32(Oa[nd][1] * inv0));
        uint2 hi = make_uint2(f2tf32(Oa[nd][2] * inv1), f2tf32(Oa[nd][3] * inv1));
        *(uint2*)&ab[(size_t)lq * NXX + nd * 8 + (lr << 1)] = lo;
        *(uint2*)&ab[(size_t)(lq + 8) * NXX + nd * 8 + (lr << 1)] = hi;
    }
}

// ---------------------------------------------------------------------------
extern "C" void kernel_launch(void* const* d_in, const int* in_sizes, int n_in,
                              void* d_out, int out_size)
{
    const float* x      = (const float*)d_in[0];
    const float* vis    = (const float*)d_in[1];
    const float* tags   = (const float*)d_in[2];
    const float* W_attn = (const float*)d_in[3];
    const float* b_attn = (const float*)d_in[4];
    const float* W_vis  = (const float*)d_in[5];
    const float* b_vis  = (const float*)d_in[6];
    const float* W_tags = (const float*)d_in[7];
    const float* b_tags = (const float*)d_in[8];
    const float* W_proj = (const float*)d_in[9];
    const float* b_proj = (const float*)d_in[10];

    float* out = (float*)d_out;
    float* present = out + (size_t)BB * SS * NXX;   // a first, then present

    static float *wt_base = nullptr, *xc = nullptr, *vc = nullptr, *ga = nullptr;
    const int DSM = 71680;                  // 2 stages x 35840 (champion GEMM)
    const int DSM_ATTN = 2 * PAIRW * 4;     // 75776
    if (!wt_base) {
        cudaGetSymbolAddress((void**)&wt_base, g_wt);
        cudaGetSymbolAddress((void**)&xc, g_xc);
        cudaGetSymbolAddress((void**)&vc, g_vc);
        cudaGetSymbolAddress((void**)&ga, g_a);
        cudaFuncSetAttribute(mma_gemm<0>, cudaFuncAttributeMaxDynamicSharedMemorySize, DSM);
        cudaFuncSetAttribute(mma_gemm<1>, cudaFuncAttributeMaxDynamicSharedMemorySize, DSM);
        cudaFuncSetAttribute(mma_gemm<3>, cudaFuncAttributeMaxDynamicSharedMemorySize, DSM);
        cudaFuncSetAttribute(attn_mma, cudaFuncAttributeMaxDynamicSharedMemorySize, DSM_ATTN);
    }
    float* wt_attn = wt_base + OFF_WT_ATTN;
    float* wt_vis  = wt_base + OFF_WT_VIS;
    float* wt_proj = wt_base + OFF_WT_PROJ;

    // Pre-round weights and activations to tf32 (one merged launch)
    cvt_tf32_multi<<<3072 + 2048 + 1024 + 8192 + 392, 256>>>(
        W_attn, wt_attn, 3072,
        W_vis,  wt_vis,  2048,
        W_proj, wt_proj, 1024,
        x,      xc,      8192,
        vis,    vc,      392);

    // QKV: [8192,1024] @ [1024,3072]
    mma_gemm<0><<<dim3(3072 / 128, 8192 / 128), 256, DSM>>>(
        xc, wt_attn, b_attn, present, nullptr, BB * SS, 3 * NXX, NXX);
    // visual: [392,1024] @ [1024,2048]
    mma_gemm<1><<<dim3(2048 / 128, 4), 256, DSM>>>(
        vc, wt_vis, b_vis, present, nullptr, BB * NVV, 2 * NXX, 1024);
    // tags: [112,400] @ [400,2048]  (FFMA)
    gemm_kernel<2><<<dim3(2048 / 128, 1), 256>>>(
        tags, W_tags, b_tags, present, nullptr, BB * NTT, 2 * NXX, 400);
    // attention (tf32 mma, single-barrier double-buffered pipeline)
    attn_mma<<<dim3(SS / 64, HH, BB), 128, DSM_ATTN>>>();
    // proj: [8192,1024] @ [1024,1024]
    mma_gemm<3><<<dim3(1024 / 128, 8192 / 128), 256, DSM>>>(
        ga, wt_proj, b_proj, nullptr, out, BB * SS, NXX, NXX);
}

// round 15
// speedup vs baseline: 1.1055x; 1.0882x over previous
#include <cuda_runtime.h>
#include <cstdint>

// Problem constants
#define BB   8
#define SS   1024
#define NXX  1024
#define HH   16
#define DHH  64
#define NVV  49
#define NTT  14
#define NSS  1087          // 14 + 49 + 1024
#define NSSP 1088          // padded stride for g_kv (padding row stays zero)
#define PREF 63            // tags + visual prefix length
#define KTAG 416           // tags K padded 400 -> 416 (multiple of 32)

// Scratch (device globals: allocation-free per harness rules)
__device__ float g_q[(size_t)BB * HH * SS * DHH];       // Q, pre-scaled+tf32
__device__ float g_a[(size_t)BB * SS * NXX];            // attn out (tf32-rounded)
__device__ float g_wt[(size_t)6144 * 1024];             // tf32 W_attn|W_vis|W_proj
__device__ float g_wtg[(size_t)KTAG * 2048];            // tf32 W_tags, K-padded
__device__ float g_tc[(size_t)BB * NTT * KTAG];         // tf32 tags, K-padded
__device__ float g_xc[(size_t)BB * SS * NXX];           // tf32 x
__device__ float g_vc[(size_t)BB * NVV * 1024];         // tf32 visual
__device__ float g_kv[(size_t)BB * 2 * HH * NSSP * DHH];// tf32 K/V, padded stride
#define OFF_WT_ATTN 0
#define OFF_WT_VIS  (3072 * 1024)
#define OFF_WT_PROJ (5120 * 1024)

// ---------------------------------------------------------------------------
__device__ __forceinline__ uint32_t f2tf32(float x) {
    uint32_t y;
    asm("cvt.rna.tf32.f32 %0, %1;" : "=r"(y) : "f"(x));
    return y;
}

__device__ __forceinline__ void mma_tf32(float* c, const uint32_t* a, const uint32_t* b) {
    asm volatile(
        "mma.sync.aligned.m16n8k8.row.col.f32.tf32.tf32.f32 "
        "{%0,%1,%2,%3}, {%4,%5,%6,%7}, {%8,%9}, {%0,%1,%2,%3};\n"
        : "+f"(c[0]), "+f"(c[1]), "+f"(c[2]), "+f"(c[3])
        : "r"(a[0]), "r"(a[1]), "r"(a[2]), "r"(a[3]), "r"(b[0]), "r"(b[1]));
}

__device__ __forceinline__ uint32_t smem_u32(const void* p) {
    uint32_t a;
    asm("{ .reg .u64 t; cvta.to.shared.u64 t, %1; cvt.u32.u64 %0, t; }"
        : "=r"(a) : "l"(p));
    return a;
}

// ---------------------------------------------------------------------------
// Merged tf32 rounding prep: one launch, 5 regions (block-index dispatch).
// ---------------------------------------------------------------------------
__global__ __launch_bounds__(256) void cvt_tf32_multi(
    const float* s0, float* d0, int b0,
    const float* s1, float* d1, int b1,
    const float* s2, float* d2, int b2,
    const float* s3, float* d3, int b3,
    const float* s4, float* d4, int b4)
{
    int blk = blockIdx.x;
    const float* src; float* dst;
    if (blk < b0)                { src = s0; dst = d0; }
    else if ((blk -= b0) < b1)   { src = s1; dst = d1; }
    else if ((blk -= b1) < b2)   { src = s2; dst = d2; }
    else if ((blk -= b2) < b3)   { src = s3; dst = d3; }
    else { blk -= b3;              src = s4; dst = d4; }
    size_t i = ((size_t)blk * 256 + threadIdx.x) * 4;
    float4 v = *(const float4*)(src + i);
    uint4 p;
    p.x = f2tf32(v.x); p.y = f2tf32(v.y);
    p.z = f2tf32(v.z); p.w = f2tf32(v.w);
    *(uint4*)(dst + i) = p;
}

// W_tags pad+cvt: [400,2048] -> [416,2048] tf32 (rows >=400 zero)
__global__ __launch_bounds__(256) void pad_wtags(const float* __restrict__ in)
{
    size_t i = ((size_t)blockIdx.x * 256 + threadIdx.x) * 4;   // over 416*2048
    int r = (int)(i >> 11);
    uint4 p = make_uint4(0u, 0u, 0u, 0u);
    if (r < 400) {
        float4 v = *(const float4*)(in + i);
        p.x = f2tf32(v.x); p.y = f2tf32(v.y);
        p.z = f2tf32(v.z); p.w = f2tf32(v.w);
    }
    *(uint4*)(g_wtg + i) = p;
}

// tags pad+cvt: [112,400] -> [112,416] tf32 (cols >=400 zero)
__global__ __launch_bounds__(256) void pad_tags(const float* __restrict__ in)
{
    size_t i = ((size_t)blockIdx.x * 256 + threadIdx.x) * 4;   // over 112*416
    if (i >= (size_t)BB * NTT * KTAG) return;
    int r = (int)(i / KTAG), c = (int)(i % KTAG);
    uint4 p = make_uint4(0u, 0u, 0u, 0u);
    if (c < 400) {
        float4 v = *(const float4*)(in + (size_t)r * 400 + c);
        p.x = f2tf32(v.x); p.y = f2tf32(v.y);
        p.z = f2tf32(v.z); p.w = f2tf32(v.w);
    }
    *(uint4*)(g_tc + i) = p;
}

// ---------------------------------------------------------------------------
// scatter helper: writes present (exact) plus tf32-rounded copies for attention
// ---------------------------------------------------------------------------
template <int MODE>
__device__ __forceinline__ void scatter(int r, int c, float val,
                                        float* __restrict__ present,
                                        float* __restrict__ outp)
{
    if (MODE == 0) {
        int b = r >> 10, s = r & 1023;
        int sect = c >> 10, cc = c & 1023;
        int h = cc >> 6, d = cc & 63;
        if (sect == 0) {
            g_q[((((size_t)b * HH + h) * SS + s) << 6) + d] =
                __uint_as_float(f2tf32(val * 0.125f));
        } else {
            present[(((((size_t)b * 2 + (sect - 1)) * HH + h) * NSS +
                      (PREF + s)) << 6) + d] = val;
            g_kv[(((((size_t)b * 2 + (sect - 1)) * HH + h) * NSSP +
                   (PREF + s)) << 6) + d] = __uint_as_float(f2tf32(val));
        }
    } else if (MODE == 1) {
        int b = r / NVV, p = r % NVV;
        int sect = c >> 10, cc = c & 1023;
        int h = cc >> 6, d = cc & 63;
        present[(((((size_t)b * 2 + sect) * HH + h) * NSS + (NTT + p)) << 6) + d] = val;
        g_kv[(((((size_t)b * 2 + sect) * HH + h) * NSSP + (NTT + p)) << 6) + d] =
            __uint_as_float(f2tf32(val));
    } else if (MODE == 2) {
        int b = r / NTT, p = r % NTT;
        int sect = c >> 10, cc = c & 1023;
        int h = cc >> 6, d = cc & 63;
        present[(((((size_t)b * 2 + sect) * HH + h) * NSS + p) << 6) + d] = val;
        g_kv[(((((size_t)b * 2 + sect) * HH + h) * NSSP + p) << 6) + d] =
            __uint_as_float(f2tf32(val));
    } else {
        outp[(size_t)r * NXX + c] = val;
    }
}

// ---------------------------------------------------------------------------
// tf32 mma GEMM with cp.async 2-stage pipeline (champion version).
// ---------------------------------------------------------------------------
template <int MODE>
__global__ __launch_bounds__(256, 2) void mma_gemm(
    const float* __restrict__ A, const float* __restrict__ W,
    const float* __restrict__ bias, float* __restrict__ present,
    float* __restrict__ outp, int M, int N, int K)
{
    extern __shared__ uint32_t sm[];
    const int bm = blockIdx.y, bn = blockIdx.x;
    const int tid = threadIdx.x;
    const int warp = tid >> 5, lane = tid & 31;
    const int wm = warp >> 1, wn = warp & 1;
    const int lq = lane >> 2, lr = lane & 3;

    const uint32_t sbase = smem_u32(sm);

    auto issue = [&](int s, int kt) {
        uint32_t abase = sbase + s * 35840;
        uint32_t bbase = abase + 18432;
#pragma unroll
        for (int i = 0; i < 4; i++) {
            int flat = tid + 256 * i;
            int m = flat >> 3, kc = flat & 7;
            int gm = bm * 128 + m;
            const float* src = A + (size_t)gm * K + kt + kc * 4;
            uint32_t dst = abase + m * 144 + kc * 16;
            int sz = (gm < M) ? 16 : 0;
            asm volatile("cp.async.ca.shared.global [%0], [%1], 16, %2;"
                         :: "r"(dst), "l"(src), "r"(sz));
        }
#pragma unroll
        for (int i = 0; i < 4; i++) {
            int flat = tid + 256 * i;
            int k = flat >> 5, nc = flat & 31;
            const float* src = W + (size_t)(kt + k) * N + bn * 128 + nc * 4;
            uint32_t dst = bbase + k * 544 + nc * 16;
            asm volatile("cp.async.ca.shared.global [%0], [%1], 16;"
                         :: "r"(dst), "l"(src));
        }
        asm volatile("cp.async.commit_group;");
    };

    float acc[2][8][4];
#pragma unroll
    for (int mt = 0; mt < 2; mt++)
#pragma unroll
        for (int nt = 0; nt < 8; nt++)
#pragma unroll
            for (int u = 0; u < 4; u++) acc[mt][nt][u] = 0.f;

    const int NC = K >> 5;
    issue(0, 0);
    if (NC > 1) issue(1, 32);
    else asm volatile("cp.async.commit_group;");

    for (int c = 0; c < NC; c++) {
        const int s = c & 1;
        asm volatile("cp.async.wait_group 1;" ::: "memory");
        __syncthreads();

        const uint32_t* Asw = sm + s * 8960;
        const uint32_t* Bsw = Asw + 4608;

#pragma unroll
        for (int g = 0; g < 4; g++) {
            uint32_t af[2][4];
#pragma unroll
            for (int mt = 0; mt < 2; mt++) {
                int r = wm * 32 + mt * 16 + lq;
                af[mt][0] = Asw[r * 36 + g * 8 + lr];
                af[mt][1] = Asw[(r + 8) * 36 + g * 8 + lr];
                af[mt][2] = Asw[r * 36 + g * 8 + lr + 4];
                af[mt][3] = Asw[(r + 8) * 36 + g * 8 + lr + 4];
            }
            uint32_t bf[8][2];
#pragma unroll
            for (int nt = 0; nt < 8; nt++) {
                int n = wn * 64 + nt * 8 + lq;
                bf[nt][0] = Bsw[(g * 8 + lr) * 136 + n];
                bf[nt][1] = Bsw[(g * 8 + lr + 4) * 136 + n];
            }
#pragma unroll
            for (int mt = 0; mt < 2; mt++)
#pragma unroll
                for (int nt = 0; nt < 8; nt++)
                    mma_tf32(acc[mt][nt], af[mt], bf[nt]);
        }
        __syncthreads();
        if (c + 2 < NC) issue(s, (c + 2) << 5);
        else asm volatile("cp.async.commit_group;");
    }

#pragma unroll
    for (int mt = 0; mt < 2; mt++) {
        int r0 = bm * 128 + wm * 32 + mt * 16 + lq;
#pragma unroll
        for (int nt = 0; nt < 8; nt++) {
            int c0 = bn * 128 + wn * 64 + nt * 8 + (lr << 1);
            float bz0 = bias[c0], bz1 = bias[c0 + 1];
            if (r0 < M) {
                scatter<MODE>(r0, c0,     acc[mt][nt][0] + bz0, present, outp);
                scatter<MODE>(r0, c0 + 1, acc[mt][nt][1] + bz1, present, outp);
            }
            if (r0 + 8 < M) {
                scatter<MODE>(r0 + 8, c0,     acc[mt][nt][2] + bz0, present, outp);
                scatter<MODE>(r0 + 8, c0 + 1, acc[mt][nt][3] + bz1, present, outp);
            }
        }
    }
}

// ---------------------------------------------------------------------------
// Flash attention v7 (round-14 champion): single-barrier double-buffered
// pipeline, Q fragments in registers, K stride 76 / V stride 72.
// smem: 2 x (K 64x76 + V 64x72) = 75776 B -> 3 CTAs/SM.
// ---------------------------------------------------------------------------
#define KST 76
#define VST 72
#define KTW (64 * KST)
#define VTW (64 * VST)
#define PAIRW (KTW + VTW)

__global__ __launch_bounds__(128, 3) void attn_mma()
{
    extern __shared__ uint32_t sm[];
    // layout: K0 | V0 | K1 | V1

    const int qt = (int)(gridDim.x - 1) - blockIdx.x;   // heavy blocks first
    const int h = blockIdx.y, b = blockIdx.z;
    const int tid = threadIdx.x;
    const int warp = tid >> 5, lane = tid & 31;
    const int lq = lane >> 2, lr = lane & 3;

    const float* qsrc  = g_q  + ((((size_t)b * HH + h) * SS + qt * 64) << 6);
    const char*  kbase = (const char*)(g_kv + (((((size_t)b * 2 + 0) * HH + h) * NSSP) << 6));
    const char*  vbase = (const char*)(g_kv + (((((size_t)b * 2 + 1) * HH + h) * NSSP) << 6));

    const uint32_t sbase = smem_u32(sm);
    const int tmax = qt + 1;

    // ---- stage Q through K0 buffer, pull fragments into registers ----
#pragma unroll
    for (int i = 0; i < 8; i++) {
        int c = tid + 128 * i;
        int row = c >> 4, q16 = (c & 15) << 4;
        asm volatile("cp.async.ca.shared.global [%0], [%1], 16;"
                     :: "r"(sbase + row * (KST * 4) + q16),
                        "l"((const char*)qsrc + (row << 8) + q16));
    }
    asm volatile("cp.async.commit_group;");
    asm volatile("cp.async.wait_group 0;" ::: "memory");
    __syncthreads();

    uint32_t Qf[8][4];
#pragma unroll
    for (int k0 = 0; k0 < 8; k0++) {
        const int rb = (warp * 16 + lq) * KST + k0 * 8;
        Qf[k0][0] = sm[rb + lr];
        Qf[k0][1] = sm[rb + 8 * KST + lr];
        Qf[k0][2] = sm[rb + lr + 4];
        Qf[k0][3] = sm[rb + 8 * KST + lr + 4];
    }
    __syncthreads();   // Q reads done before K0 tile overwrites buffer

    auto issue_tile = [&](int t) {
        const int s = t & 1;
        const uint32_t kd = sbase + s * PAIRW * 4;
        const uint32_t vd = kd + KTW * 4;
        const char* ks = kbase + ((size_t)t << 14);
        const char* vs = vbase + ((size_t)t << 14);
#pragma unroll
        for (int i = 0; i < 8; i++) {
            int c = tid + 128 * i;
            int row = c >> 4, q16 = (c & 15) << 4;
            int goff = (row << 8) + q16;
            asm volatile("cp.async.ca.shared.global [%0], [%1], 16;"
                         :: "r"(kd + row * (KST * 4) + q16), "l"(ks + goff));
            asm volatile("cp.async.ca.shared.global [%0], [%1], 16;"
                         :: "r"(vd + row * (VST * 4) + q16), "l"(vs + goff));
        }
        asm volatile("cp.async.commit_group;");
    };

    issue_tile(0);

    float Oa[8][4];
#pragma unroll
    for (int nd = 0; nd < 8; nd++)
#pragma unroll
        for (int u = 0; u < 4; u++) Oa[nd][u] = 0.f;
    float m0 = -1e30f, m1 = -1e30f, l0 = 0.f, l1 = 0.f;

    const int warp_r0 = qt * 64 + warp * 16;
    const int r0g = warp_r0 + lq;

    float Sa[8][4];

    for (int t = 0; t <= tmax; t++) {
        const int s = t & 1;
        const uint32_t* Ks = sm + s * PAIRW;
        const uint32_t* Vs = Ks + KTW;

        asm volatile("cp.async.wait_group 0;" ::: "memory");
        __syncthreads();

        if (t + 1 <= tmax) issue_tile(t + 1);

        // ---- S = Q K^T ----
#pragma unroll
        for (int nt = 0; nt < 8; nt++)
#pragma unroll
            for (int u = 0; u < 4; u++) Sa[nt][u] = 0.f;

#pragma unroll
        for (int k0 = 0; k0 < 8; k0++) {
#pragma unroll
            for (int nt = 0; nt < 8; nt++) {
                uint32_t bf[2];
                const int kb = (nt * 8 + lq) * KST + k0 * 8 + lr;
                bf[0] = Ks[kb];
                bf[1] = Ks[kb + 4];
                mma_tf32(Sa[nt], Qf[k0], bf);
            }
        }

        if (t * 64 + 63 > warp_r0 + PREF) {
#pragma unroll
            for (int nt = 0; nt < 8; nt++) {
                int j0 = t * 64 + nt * 8 + (lr << 1);
                if (j0     > r0g + PREF     || j0     >= NSS) Sa[nt][0] = -1e30f;
                if (j0 + 1 > r0g + PREF     || j0 + 1 >= NSS) Sa[nt][1] = -1e30f;
                if (j0     > r0g + 8 + PREF || j0     >= NSS) Sa[nt][2] = -1e30f;
                if (j0 + 1 > r0g + 8 + PREF || j0 + 1 >= NSS) Sa[nt][3] = -1e30f;
            }
        }

        // ---- online softmax ----
        float mx0 = -1e30f, mx1 = -1e30f;
#pragma unroll
        for (int nt = 0; nt < 8; nt++) {
            mx0 = fmaxf(mx0, fmaxf(Sa[nt][0], Sa[nt][1]));
            mx1 = fmaxf(mx1, fmaxf(Sa[nt][2], Sa[nt][3]));
        }
        mx0 = fmaxf(mx0, __shfl_xor_sync(0xffffffffu, mx0, 1));
        mx0 = fmaxf(mx0, __shfl_xor_sync(0xffffffffu, mx0, 2));
        mx1 = fmaxf(mx1, __shfl_xor_sync(0xffffffffu, mx1, 1));
        mx1 = fmaxf(mx1, __shfl_xor_sync(0xffffffffu, mx1, 2));
        float mn0 = fmaxf(m0, mx0), mn1 = fmaxf(m1, mx1);
        float cr0 = __expf(m0 - mn0), cr1 = __expf(m1 - mn1);
        float s0 = 0.f, s1 = 0.f;
#pragma unroll
        for (int nt = 0; nt < 8; nt++) {
            float e0 = __expf(Sa[nt][0] - mn0); Sa[nt][0] = e0; s0 += e0;
            float e1 = __expf(Sa[nt][1] - mn0); Sa[nt][1] = e1; s0 += e1;
            float e2 = __expf(Sa[nt][2] - mn1); Sa[nt][2] = e2; s1 += e2;
            float e3 = __expf(Sa[nt][3] - mn1); Sa[nt][3] = e3; s1 += e3;
        }
        s0 += __shfl_xor_sync(0xffffffffu, s0, 1);
        s0 += __shfl_xor_sync(0xffffffffu, s0, 2);
        s1 += __shfl_xor_sync(0xffffffffu, s1, 1);
        s1 += __shfl_xor_sync(0xffffffffu, s1, 2);
        l0 = l0 * cr0 + s0; l1 = l1 * cr1 + s1;
        m0 = mn0; m1 = mn1;
#pragma unroll
        for (int nd = 0; nd < 8; nd++) {
            Oa[nd][0] *= cr0; Oa[nd][1] *= cr0;
            Oa[nd][2] *= cr1; Oa[nd][3] *= cr1;
        }

        // ---- O += P V ----
        const int sA = (lane & ~3) + (lr >> 1);
        const int sB = sA + 2;
        const bool odd = lr & 1;
#pragma unroll
        for (int kt = 0; kt < 8; kt++) {
            float p0 = __shfl_sync(0xffffffffu, Sa[kt][0], sA);
            float p1 = __shfl_sync(0xffffffffu, Sa[kt][1], sA);
            float p2 = __shfl_sync(0xffffffffu, Sa[kt][2], sA);
            float p3 = __shfl_sync(0xffffffffu, Sa[kt][3], sA);
            float q0 = __shfl_sync(0xffffffffu, Sa[kt][0], sB);
            float q1 = __shfl_sync(0xffffffffu, Sa[kt][1], sB);
            float q2 = __shfl_sync(0xffffffffu, Sa[kt][2], sB);
            float q3 = __shfl_sync(0xffffffffu, Sa[kt][3], sB);
            uint32_t a[4];
            a[0] = f2tf32(odd ? p1 : p0);
            a[1] = f2tf32(odd ? p3 : p2);
            a[2] = f2tf32(odd ? q1 : q0);
            a[3] = f2tf32(odd ? q3 : q2);
#pragma unroll
            for (int nd = 0; nd < 8; nd++) {
                uint32_t bf[2];
                const int vb = (kt * 8 + lr) * VST + nd * 8 + lq;
                bf[0] = Vs[vb];
                bf[1] = Vs[vb + 4 * VST];
                mma_tf32(Oa[nd], a, bf);
            }
        }
        // no trailing barrier: next phase's wait+bar protects buffer reuse
    }

    float inv0 = 1.f / l0, inv1 = 1.f / l1;
    float* ab = g_a + ((size_t)b * SS + qt * 64 + warp * 16) * NXX + h * 64;
#pragma unroll
    for (int nd = 0; nd < 8; nd++) {
        uint2 lo = make_uint2(f2tf32(Oa[nd][0] * inv0), f2tf32(Oa[nd][1] * inv0));
        uint2 hi = make_uint2(f2tf32(Oa[nd][2] * inv1), f2tf32(Oa[nd][3] * inv1));
        *(uint2*)&ab[(size_t)lq * NXX + nd * 8 + (lr << 1)] = lo;
        *(uint2*)&ab[(size_t)(lq + 8) * NXX + nd * 8 + (lr << 1)] = hi;
    }
}

// ---------------------------------------------------------------------------
extern "C" void kernel_launch(void* const* d_in, const int* in_sizes, int n_in,
                              void* d_out, int out_size)
{
    const float* x      = (const float*)d_in[0];
    const float* vis    = (const float*)d_in[1];
    const float* tags   = (const float*)d_in[2];
    const float* W_attn = (const float*)d_in[3];
    const float* b_attn = (const float*)d_in[4];
    const float* W_vis  = (const float*)d_in[5];
    const float* b_vis  = (const float*)d_in[6];
    const float* W_tags = (const float*)d_in[7];
    const float* b_tags = (const float*)d_in[8];
    const float* W_proj = (const float*)d_in[9];
    const float* b_proj = (const float*)d_in[10];

    float* out = (float*)d_out;
    float* present = out + (size_t)BB * SS * NXX;   // a first, then present

    static float *wt_base = nullptr, *xc = nullptr, *vc = nullptr, *ga = nullptr;
    static float *wtg = nullptr, *tc = nullptr;
    const int DSM = 71680;
    const int DSM_ATTN = 2 * PAIRW * 4;     // 75776
    if (!wt_base) {
        cudaGetSymbolAddress((void**)&wt_base, g_wt);
        cudaGetSymbolAddress((void**)&xc, g_xc);
        cudaGetSymbolAddress((void**)&vc, g_vc);
        cudaGetSymbolAddress((void**)&ga, g_a);
        cudaGetSymbolAddress((void**)&wtg, g_wtg);
        cudaGetSymbolAddress((void**)&tc, g_tc);
        cudaFuncSetAttribute(mma_gemm<0>, cudaFuncAttributeMaxDynamicSharedMemorySize, DSM);
        cudaFuncSetAttribute(mma_gemm<1>, cudaFuncAttributeMaxDynamicSharedMemorySize, DSM);
        cudaFuncSetAttribute(mma_gemm<2>, cudaFuncAttributeMaxDynamicSharedMemorySize, DSM);
        cudaFuncSetAttribute(mma_gemm<3>, cudaFuncAttributeMaxDynamicSharedMemorySize, DSM);
        cudaFuncSetAttribute(attn_mma, cudaFuncAttributeMaxDynamicSharedMemorySize, DSM_ATTN);
    }
    float* wt_attn = wt_base + OFF_WT_ATTN;
    float* wt_vis  = wt_base + OFF_WT_VIS;
    float* wt_proj = wt_base + OFF_WT_PROJ;

    // Pre-round weights and activations to tf32 (one merged launch)
    cvt_tf32_multi<<<3072 + 2048 + 1024 + 8192 + 392, 256>>>(
        W_attn, wt_attn, 3072,
        W_vis,  wt_vis,  2048,
        W_proj, wt_proj, 1024,
        x,      xc,      8192,
        vis,    vc,      392);
    // tags K-pad prep (400 -> 416 with zeros)
    pad_wtags<<<(KTAG * 2048) / 1024, 256>>>(W_tags);
    pad_tags<<<(BB * NTT * KTAG + 1023) / 1024, 256>>>(tags);

    // QKV: [8192,1024] @ [1024,3072]
    mma_gemm<0><<<dim3(3072 / 128, 8192 / 128), 256, DSM>>>(
        xc, wt_attn, b_attn, present, nullptr, BB * SS, 3 * NXX, NXX);
    // visual: [392,1024] @ [1024,2048]
    mma_gemm<1><<<dim3(2048 / 128, 4), 256, DSM>>>(
        vc, wt_vis, b_vis, present, nullptr, BB * NVV, 2 * NXX, 1024);
    // tags: [112,416] @ [416,2048]  (tf32 mma, zero-padded K)
    mma_gemm<2><<<dim3(2048 / 128, 1), 256, DSM>>>(
        tc, wtg, b_tags, present, nullptr, BB * NTT, 2 * NXX, KTAG);
    // attention (tf32 mma, single-barrier double-buffered pipeline)
    attn_mma<<<dim3(SS / 64, HH, BB), 128, DSM_ATTN>>>();
    // proj: [8192,1024] @ [1024,1024]
    mma_gemm<3><<<dim3(1024 / 128, 8192 / 128), 256, DSM>>>(
        ga, wt_proj, b_proj, nullptr, out, BB * SS, NXX, NXX);
}

// round 16
// speedup vs baseline: 1.2052x; 1.0902x over previous
#include <cuda_runtime.h>
#include <cstdint>

// Problem constants
#define BB   8
#define SS   1024
#define NXX  1024
#define HH   16
#define DHH  64
#define NVV  49
#define NTT  14
#define NSS  1087          // 14 + 49 + 1024
#define NSSP 1088          // padded stride for g_kv (padding row stays zero)
#define PREF 63            // tags + visual prefix length
#define KTAG 416           // tags K padded 400 -> 416 (multiple of 32)

// Scratch (device globals: allocation-free per harness rules)
__device__ float g_q[(size_t)BB * HH * SS * DHH];       // Q, pre-scaled+tf32
__device__ float g_a[(size_t)BB * SS * NXX];            // attn out (tf32-rounded)
__device__ float g_wt[(size_t)6144 * 1024];             // tf32 weights, TRANSPOSED [N][K]
__device__ float g_wtg[(size_t)2048 * KTAG];            // tf32 W_tags^T [2048][416]
__device__ float g_tc[(size_t)BB * NTT * KTAG];         // tf32 tags, K-padded
__device__ float g_xc[(size_t)BB * SS * NXX];           // tf32 x
__device__ float g_vc[(size_t)BB * NVV * 1024];         // tf32 visual
__device__ float g_kv[(size_t)BB * 2 * HH * NSSP * DHH];// tf32 K/V, padded stride
#define OFF_WT_ATTN 0
#define OFF_WT_VIS  (3072 * 1024)
#define OFF_WT_PROJ (5120 * 1024)

// ---------------------------------------------------------------------------
__device__ __forceinline__ uint32_t f2tf32(float x) {
    uint32_t y;
    asm("cvt.rna.tf32.f32 %0, %1;" : "=r"(y) : "f"(x));
    return y;
}

__device__ __forceinline__ void mma_tf32(float* c, const uint32_t* a, const uint32_t* b) {
    asm volatile(
        "mma.sync.aligned.m16n8k8.row.col.f32.tf32.tf32.f32 "
        "{%0,%1,%2,%3}, {%4,%5,%6,%7}, {%8,%9}, {%0,%1,%2,%3};\n"
        : "+f"(c[0]), "+f"(c[1]), "+f"(c[2]), "+f"(c[3])
        : "r"(a[0]), "r"(a[1]), "r"(a[2]), "r"(a[3]), "r"(b[0]), "r"(b[1]));
}

__device__ __forceinline__ void ldsm_x4(uint32_t* r, uint32_t addr) {
    asm volatile(
        "ldmatrix.sync.aligned.m8n8.x4.shared.b16 {%0,%1,%2,%3}, [%4];"
        : "=r"(r[0]), "=r"(r[1]), "=r"(r[2]), "=r"(r[3]) : "r"(addr));
}

__device__ __forceinline__ uint32_t smem_u32(const void* p) {
    uint32_t a;
    asm("{ .reg .u64 t; cvta.to.shared.u64 t, %1; cvt.u32.u64 %0, t; }"
        : "=r"(a) : "l"(p));
    return a;
}

// ---------------------------------------------------------------------------
// Prep: tiled transpose + tf32 cvt.  in W[k][n] (Kin real rows) -> out Wt[n][k]
// (K padded rows, zeros for k >= Kin).  Grid (K/32, N/32), 256 threads.
// ---------------------------------------------------------------------------
__global__ __launch_bounds__(256) void transpose_cvt(
    const float* __restrict__ in, float* __restrict__ out, int K, int N, int Kin)
{
    __shared__ float t[32][33];
    int k0 = blockIdx.x * 32, n0 = blockIdx.y * 32;
    int tx = threadIdx.x & 31, ty = threadIdx.x >> 5;
#pragma unroll
    for (int r = 0; r < 4; r++) {
        int k = k0 + ty + 8 * r;
        t[ty + 8 * r][tx] = (k < Kin) ? in[(size_t)k * N + n0 + tx] : 0.f;
    }
    __syncthreads();
#pragma unroll
    for (int r = 0; r < 4; r++)
        out[(size_t)(n0 + ty + 8 * r) * K + k0 + tx] =
            __uint_as_float(f2tf32(t[tx][ty + 8 * r]));
}

// Activation tf32 cvt (x + vis merged, block dispatch)
__global__ __launch_bounds__(256) void cvt_act(
    const float* s0, float* d0, int b0, const float* s1, float* d1)
{
    int blk = blockIdx.x;
    const float* src; float* dst;
    if (blk < b0) { src = s0; dst = d0; } else { blk -= b0; src = s1; dst = d1; }
    size_t i = ((size_t)blk * 256 + threadIdx.x) * 4;
    float4 v = *(const float4*)(src + i);
    uint4 p;
    p.x = f2tf32(v.x); p.y = f2tf32(v.y);
    p.z = f2tf32(v.z); p.w = f2tf32(v.w);
    *(uint4*)(dst + i) = p;
}

// tags pad+cvt: [112,400] -> [112,416] tf32 (cols >=400 zero)
__global__ __launch_bounds__(256) void pad_tags(const float* __restrict__ in)
{
    size_t i = ((size_t)blockIdx.x * 256 + threadIdx.x) * 4;
    if (i >= (size_t)BB * NTT * KTAG) return;
    int r = (int)(i / KTAG), c = (int)(i % KTAG);
    uint4 p = make_uint4(0u, 0u, 0u, 0u);
    if (c < 400) {
        float4 v = *(const float4*)(in + (size_t)r * 400 + c);
        p.x = f2tf32(v.x); p.y = f2tf32(v.y);
        p.z = f2tf32(v.z); p.w = f2tf32(v.w);
    }
    *(uint4*)(g_tc + i) = p;
}

// ---------------------------------------------------------------------------
// scatter helper: writes present (exact) plus tf32-rounded copies for attention
// ---------------------------------------------------------------------------
template <int MODE>
__device__ __forceinline__ void scatter(int r, int c, float val,
                                        float* __restrict__ present,
                                        float* __restrict__ outp)
{
    if (MODE == 0) {
        int b = r >> 10, s = r & 1023;
        int sect = c >> 10, cc = c & 1023;
        int h = cc >> 6, d = cc & 63;
        if (sect == 0) {
            g_q[((((size_t)b * HH + h) * SS + s) << 6) + d] =
                __uint_as_float(f2tf32(val * 0.125f));
        } else {
            present[(((((size_t)b * 2 + (sect - 1)) * HH + h) * NSS +
                      (PREF + s)) << 6) + d] = val;
            g_kv[(((((size_t)b * 2 + (sect - 1)) * HH + h) * NSSP +
                   (PREF + s)) << 6) + d] = __uint_as_float(f2tf32(val));
        }
    } else if (MODE == 1) {
        int b = r / NVV, p = r % NVV;
        int sect = c >> 10, cc = c & 1023;
        int h = cc >> 6, d = cc & 63;
        present[(((((size_t)b * 2 + sect) * HH + h) * NSS + (NTT + p)) << 6) + d] = val;
        g_kv[(((((size_t)b * 2 + sect) * HH + h) * NSSP + (NTT + p)) << 6) + d] =
            __uint_as_float(f2tf32(val));
    } else if (MODE == 2) {
        int b = r / NTT, p = r % NTT;
        int sect = c >> 10, cc = c & 1023;
        int h = cc >> 6, d = cc & 63;
        present[(((((size_t)b * 2 + sect) * HH + h) * NSS + p) << 6) + d] = val;
        g_kv[(((((size_t)b * 2 + sect) * HH + h) * NSSP + p) << 6) + d] =
            __uint_as_float(f2tf32(val));
    } else {
        outp[(size_t)r * NXX + c] = val;
    }
}

// ---------------------------------------------------------------------------
// tf32 mma GEMM, ldmatrix fragments, cp.async 2-stage pipeline.
// C[M,N] = A[M,K] @ Wt^T + bias, Wt is [N][K] row-major (both tiles k-major).
// BM=BN=128, BK=32, 256 threads (4x2 warps, 32x64 per warp). K%32==0, N%128==0.
// stage = A 128x36 + B 128x36 words = 36864 B; 2 stages = 73728 B.
// ---------------------------------------------------------------------------
template <int MODE>
__global__ __launch_bounds__(256, 2) void mma_gemm(
    const float* __restrict__ A, const float* __restrict__ Wt,
    const float* __restrict__ bias, float* __restrict__ present,
    float* __restrict__ outp, int M, int N, int K)
{
    extern __shared__ uint32_t sm[];
    const int bm = blockIdx.y, bn = blockIdx.x;
    const int tid = threadIdx.x;
    const int warp = tid >> 5, lane = tid & 31;
    const int wm = warp >> 1, wn = warp & 1;
    const int lq = lane >> 2, lr = lane & 3;

    const uint32_t sbase = smem_u32(sm);

    auto issue = [&](int s, int kt) {
        uint32_t abase = sbase + s * 36864;
        uint32_t bbase = abase + 18432;
#pragma unroll
        for (int i = 0; i < 4; i++) {
            int flat = tid + 256 * i;
            int m = flat >> 3, kc = flat & 7;
            int gm = bm * 128 + m;
            const float* src = A + (size_t)gm * K + kt + kc * 4;
            uint32_t dst = abase + m * 144 + kc * 16;
            int sz = (gm < M) ? 16 : 0;
            asm volatile("cp.async.ca.shared.global [%0], [%1], 16, %2;"
                         :: "r"(dst), "l"(src), "r"(sz));
        }
#pragma unroll
        for (int i = 0; i < 4; i++) {
            int flat = tid + 256 * i;
            int n = flat >> 3, kc = flat & 7;
            const float* src = Wt + (size_t)(bn * 128 + n) * K + kt + kc * 4;
            uint32_t dst = bbase + n * 144 + kc * 16;
            asm volatile("cp.async.ca.shared.global [%0], [%1], 16;"
                         :: "r"(dst), "l"(src));
        }
        asm volatile("cp.async.commit_group;");
    };

    // ldmatrix per-lane tile offsets (bytes, within stage)
    const int lt = lane >> 3, rr = lane & 7;
    const uint32_t aoff = (uint32_t)(((wm * 32 + (lt & 1) * 8 + rr) * 36 +
                                      (lt >> 1) * 4) * 4);
    const uint32_t boff = (uint32_t)(((wn * 64 + (lt >> 1) * 8 + rr) * 36 +
                                      (lt & 1) * 4) * 4);

    float acc[2][8][4];
#pragma unroll
    for (int mt = 0; mt < 2; mt++)
#pragma unroll
        for (int nt = 0; nt < 8; nt++)
#pragma unroll
            for (int u = 0; u < 4; u++) acc[mt][nt][u] = 0.f;

    const int NC = K >> 5;
    issue(0, 0);
    if (NC > 1) issue(1, 32);
    else asm volatile("cp.async.commit_group;");

    for (int c = 0; c < NC; c++) {
        const int s = c & 1;
        asm volatile("cp.async.wait_group 1;" ::: "memory");
        __syncthreads();

        const uint32_t stA = sbase + s * 36864;
        const uint32_t stB = stA + 18432;

#pragma unroll
        for (int g = 0; g < 4; g++) {
            uint32_t af[2][4];
            ldsm_x4(af[0], stA + aoff + g * 32);
            ldsm_x4(af[1], stA + aoff + 2304 + g * 32);   // +16 rows * 144B
            uint32_t bf[8][2];
#pragma unroll
            for (int p = 0; p < 4; p++) {
                uint32_t tmp[4];
                ldsm_x4(tmp, stB + boff + p * 2304 + g * 32);
                bf[2 * p][0] = tmp[0]; bf[2 * p][1] = tmp[1];
                bf[2 * p + 1][0] = tmp[2]; bf[2 * p + 1][1] = tmp[3];
            }
#pragma unroll
            for (int mt = 0; mt < 2; mt++)
#pragma unroll
                for (int nt = 0; nt < 8; nt++)
                    mma_tf32(acc[mt][nt], af[mt], bf[nt]);
        }
        __syncthreads();
        if (c + 2 < NC) issue(s, (c + 2) << 5);
        else asm volatile("cp.async.commit_group;");
    }

#pragma unroll
    for (int mt = 0; mt < 2; mt++) {
        int r0 = bm * 128 + wm * 32 + mt * 16 + lq;
#pragma unroll
        for (int nt = 0; nt < 8; nt++) {
            int c0 = bn * 128 + wn * 64 + nt * 8 + (lr << 1);
            float bz0 = bias[c0], bz1 = bias[c0 + 1];
            if (r0 < M) {
                scatter<MODE>(r0, c0,     acc[mt][nt][0] + bz0, present, outp);
                scatter<MODE>(r0, c0 + 1, acc[mt][nt][1] + bz1, present, outp);
            }
            if (r0 + 8 < M) {
                scatter<MODE>(r0 + 8, c0,     acc[mt][nt][2] + bz0, present, outp);
                scatter<MODE>(r0 + 8, c0 + 1, acc[mt][nt][3] + bz1, present, outp);
            }
        }
    }
}

// ---------------------------------------------------------------------------
// Flash attention v7 (champion): single-barrier double-buffered pipeline,
// Q fragments in registers, K stride 76 / V stride 72. 75776 B -> 3 CTAs/SM.
// ---------------------------------------------------------------------------
#define KST 76
#define VST 72
#define KTW (64 * KST)
#define VTW (64 * VST)
#define PAIRW (KTW + VTW)

__global__ __launch_bounds__(128, 3) void attn_mma()
{
    extern __shared__ uint32_t sm[];
    const int qt = (int)(gridDim.x - 1) - blockIdx.x;
    const int h = blockIdx.y, b = blockIdx.z;
    const int tid = threadIdx.x;
    const int warp = tid >> 5, lane = tid & 31;
    const int lq = lane >> 2, lr = lane & 3;

    const float* qsrc  = g_q  + ((((size_t)b * HH + h) * SS + qt * 64) << 6);
    const char*  kbase = (const char*)(g_kv + (((((size_t)b * 2 + 0) * HH + h) * NSSP) << 6));
    const char*  vbase = (const char*)(g_kv + (((((size_t)b * 2 + 1) * HH + h) * NSSP) << 6));

    const uint32_t sbase = smem_u32(sm);
    const int tmax = qt + 1;

#pragma unroll
    for (int i = 0; i < 8; i++) {
        int c = tid + 128 * i;
        int row = c >> 4, q16 = (c & 15) << 4;
        asm volatile("cp.async.ca.shared.global [%0], [%1], 16;"
                     :: "r"(sbase + row * (KST * 4) + q16),
                        "l"((const char*)qsrc + (row << 8) + q16));
    }
    asm volatile("cp.async.commit_group;");
    asm volatile("cp.async.wait_group 0;" ::: "memory");
    __syncthreads();

    uint32_t Qf[8][4];
#pragma unroll
    for (int k0 = 0; k0 < 8; k0++) {
        const int rb = (warp * 16 + lq) * KST + k0 * 8;
        Qf[k0][0] = sm[rb + lr];
        Qf[k0][1] = sm[rb + 8 * KST + lr];
        Qf[k0][2] = sm[rb + lr + 4];
        Qf[k0][3] = sm[rb + 8 * KST + lr + 4];
    }
    __syncthreads();

    auto issue_tile = [&](int t) {
        const int s = t & 1;
        const uint32_t kd = sbase + s * PAIRW * 4;
        const uint32_t vd = kd + KTW * 4;
        const char* ks = kbase + ((size_t)t << 14);
        const char* vs = vbase + ((size_t)t << 14);
#pragma unroll
        for (int i = 0; i < 8; i++) {
            int c = tid + 128 * i;
            int row = c >> 4, q16 = (c & 15) << 4;
            int goff = (row << 8) + q16;
            asm volatile("cp.async.ca.shared.global [%0], [%1], 16;"
                         :: "r"(kd + row * (KST * 4) + q16), "l"(ks + goff));
            asm volatile("cp.async.ca.shared.global [%0], [%1], 16;"
                         :: "r"(vd + row * (VST * 4) + q16), "l"(vs + goff));
        }
        asm volatile("cp.async.commit_group;");
    };

    issue_tile(0);

    float Oa[8][4];
#pragma unroll
    for (int nd = 0; nd < 8; nd++)
#pragma unroll
        for (int u = 0; u < 4; u++) Oa[nd][u] = 0.f;
    float m0 = -1e30f, m1 = -1e30f, l0 = 0.f, l1 = 0.f;

    const int warp_r0 = qt * 64 + warp * 16;
    const int r0g = warp_r0 + lq;

    float Sa[8][4];

    for (int t = 0; t <= tmax; t++) {
        const int s = t & 1;
        const uint32_t* Ks = sm + s * PAIRW;
        const uint32_t* Vs = Ks + KTW;

        asm volatile("cp.async.wait_group 0;" ::: "memory");
        __syncthreads();

        if (t + 1 <= tmax) issue_tile(t + 1);

#pragma unroll
        for (int nt = 0; nt < 8; nt++)
#pragma unroll
            for (int u = 0; u < 4; u++) Sa[nt][u] = 0.f;

#pragma unroll
        for (int k0 = 0; k0 < 8; k0++) {
#pragma unroll
            for (int nt = 0; nt < 8; nt++) {
                uint32_t bf[2];
                const int kb = (nt * 8 + lq) * KST + k0 * 8 + lr;
                bf[0] = Ks[kb];
                bf[1] = Ks[kb + 4];
                mma_tf32(Sa[nt], Qf[k0], bf);
            }
        }

        if (t * 64 + 63 > warp_r0 + PREF) {
#pragma unroll
            for (int nt = 0; nt < 8; nt++) {
                int j0 = t * 64 + nt * 8 + (lr << 1);
                if (j0     > r0g + PREF     || j0     >= NSS) Sa[nt][0] = -1e30f;
                if (j0 + 1 > r0g + PREF     || j0 + 1 >= NSS) Sa[nt][1] = -1e30f;
                if (j0     > r0g + 8 + PREF || j0     >= NSS) Sa[nt][2] = -1e30f;
                if (j0 + 1 > r0g + 8 + PREF || j0 + 1 >= NSS) Sa[nt][3] = -1e30f;
            }
        }

        float mx0 = -1e30f, mx1 = -1e30f;
#pragma unroll
        for (int nt = 0; nt < 8; nt++) {
            mx0 = fmaxf(mx0, fmaxf(Sa[nt][0], Sa[nt][1]));
            mx1 = fmaxf(mx1, fmaxf(Sa[nt][2], Sa[nt][3]));
        }
        mx0 = fmaxf(mx0, __shfl_xor_sync(0xffffffffu, mx0, 1));
        mx0 = fmaxf(mx0, __shfl_xor_sync(0xffffffffu, mx0, 2));
        mx1 = fmaxf(mx1, __shfl_xor_sync(0xffffffffu, mx1, 1));
        mx1 = fmaxf(mx1, __shfl_xor_sync(0xffffffffu, mx1, 2));
        float mn0 = fmaxf(m0, mx0), mn1 = fmaxf(m1, mx1);
        float cr0 = __expf(m0 - mn0), cr1 = __expf(m1 - mn1);
        float s0 = 0.f, s1 = 0.f;
#pragma unroll
        for (int nt = 0; nt < 8; nt++) {
            float e0 = __expf(Sa[nt][0] - mn0); Sa[nt][0] = e0; s0 += e0;
            float e1 = __expf(Sa[nt][1] - mn0); Sa[nt][1] = e1; s0 += e1;
            float e2 = __expf(Sa[nt][2] - mn1); Sa[nt][2] = e2; s1 += e2;
            float e3 = __expf(Sa[nt][3] - mn1); Sa[nt][3] = e3; s1 += e3;
        }
        s0 += __shfl_xor_sync(0xffffffffu, s0, 1);
        s0 += __shfl_xor_sync(0xffffffffu, s0, 2);
        s1 += __shfl_xor_sync(0xffffffffu, s1, 1);
        s1 += __shfl_xor_sync(0xffffffffu, s1, 2);
        l0 = l0 * cr0 + s0; l1 = l1 * cr1 + s1;
        m0 = mn0; m1 = mn1;
#pragma unroll
        for (int nd = 0; nd < 8; nd++) {
            Oa[nd][0] *= cr0; Oa[nd][1] *= cr0;
            Oa[nd][2] *= cr1; Oa[nd][3] *= cr1;
        }

        const int sA = (lane & ~3) + (lr >> 1);
        const int sB = sA + 2;
        const bool odd = lr & 1;
#pragma unroll
        for (int kt = 0; kt < 8; kt++) {
            float p0 = __shfl_sync(0xffffffffu, Sa[kt][0], sA);
            float p1 = __shfl_sync(0xffffffffu, Sa[kt][1], sA);
            float p2 = __shfl_sync(0xffffffffu, Sa[kt][2], sA);
            float p3 = __shfl_sync(0xffffffffu, Sa[kt][3], sA);
            float q0 = __shfl_sync(0xffffffffu, Sa[kt][0], sB);
            float q1 = __shfl_sync(0xffffffffu, Sa[kt][1], sB);
            float q2 = __shfl_sync(0xffffffffu, Sa[kt][2], sB);
            float q3 = __shfl_sync(0xffffffffu, Sa[kt][3], sB);
            uint32_t a[4];
            a[0] = f2tf32(odd ? p1 : p0);
            a[1] = f2tf32(odd ? p3 : p2);
            a[2] = f2tf32(odd ? q1 : q0);
            a[3] = f2tf32(odd ? q3 : q2);
#pragma unroll
            for (int nd = 0; nd < 8; nd++) {
                uint32_t bf[2];
                const int vb = (kt * 8 + lr) * VST + nd * 8 + lq;
                bf[0] = Vs[vb];
                bf[1] = Vs[vb + 4 * VST];
                mma_tf32(Oa[nd], a, bf);
            }
        }
    }

    float inv0 = 1.f / l0, inv1 = 1.f / l1;
    float* ab = g_a + ((size_t)b * SS + qt * 64 + warp * 16) * NXX + h * 64;
#pragma unroll
    for (int nd = 0; nd < 8; nd++) {
        uint2 lo = make_uint2(f2tf32(Oa[nd][0] * inv0), f2tf32(Oa[nd][1] * inv0));
        uint2 hi = make_uint2(f2tf32(Oa[nd][2] * inv1), f2tf32(Oa[nd][3] * inv1));
        *(uint2*)&ab[(size_t)lq * NXX + nd * 8 + (lr << 1)] = lo;
        *(uint2*)&ab[(size_t)(lq + 8) * NXX + nd * 8 + (lr << 1)] = hi;
    }
}

// ---------------------------------------------------------------------------
extern "C" void kernel_launch(void* const* d_in, const int* in_sizes, int n_in,
                              void* d_out, int out_size)
{
    const float* x      = (const float*)d_in[0];
    const float* vis    = (const float*)d_in[1];
    const float* tags   = (const float*)d_in[2];
    const float* W_attn = (const float*)d_in[3];
    const float* b_attn = (const float*)d_in[4];
    const float* W_vis  = (const float*)d_in[5];
    const float* b_vis  = (const float*)d_in[6];
    const float* W_tags = (const float*)d_in[7];
    const float* b_tags = (const float*)d_in[8];
    const float* W_proj = (const float*)d_in[9];
    const float* b_proj = (const float*)d_in[10];

    float* out = (float*)d_out;
    float* present = out + (size_t)BB * SS * NXX;   // a first, then present

    static float *wt_base = nullptr, *xc = nullptr, *vc = nullptr, *ga = nullptr;
    static float *wtg = nullptr, *tc = nullptr;
    const int DSM = 73728;                  // 2 stages x 36864
    const int DSM_ATTN = 2 * PAIRW * 4;     // 75776
    if (!wt_base) {
        cudaGetSymbolAddress((void**)&wt_base, g_wt);
        cudaGetSymbolAddress((void**)&xc, g_xc);
        cudaGetSymbolAddress((void**)&vc, g_vc);
        cudaGetSymbolAddress((void**)&ga, g_a);
        cudaGetSymbolAddress((void**)&wtg, g_wtg);
        cudaGetSymbolAddress((void**)&tc, g_tc);
        cudaFuncSetAttribute(mma_gemm<0>, cudaFuncAttributeMaxDynamicSharedMemorySize, DSM);
        cudaFuncSetAttribute(mma_gemm<1>, cudaFuncAttributeMaxDynamicSharedMemorySize, DSM);
        cudaFuncSetAttribute(mma_gemm<2>, cudaFuncAttributeMaxDynamicSharedMemorySize, DSM);
        cudaFuncSetAttribute(mma_gemm<3>, cudaFuncAttributeMaxDynamicSharedMemorySize, DSM);
        cudaFuncSetAttribute(attn_mma, cudaFuncAttributeMaxDynamicSharedMemorySize, DSM_ATTN);
    }
    float* wt_attn = wt_base + OFF_WT_ATTN;
    float* wt_vis  = wt_base + OFF_WT_VIS;
    float* wt_proj = wt_base + OFF_WT_PROJ;

    // Prep: transpose+cvt weights; cvt activations; pad tags
    transpose_cvt<<<dim3(32, 96), 256>>>(W_attn, wt_attn, 1024, 3072, 1024);
    transpose_cvt<<<dim3(32, 64), 256>>>(W_vis,  wt_vis,  1024, 2048, 1024);
    transpose_cvt<<<dim3(32, 32), 256>>>(W_proj, wt_proj, 1024, 1024, 1024);
    transpose_cvt<<<dim3(KTAG / 32, 64), 256>>>(W_tags, wtg, KTAG, 2048, 400);
    cvt_act<<<8192 + 392, 256>>>(x, xc, 8192, vis, vc);
    pad_tags<<<(BB * NTT * KTAG + 1023) / 1024, 256>>>(tags);

    // QKV: [8192,1024] @ [1024,3072]
    mma_gemm<0><<<dim3(3072 / 128, 8192 / 128), 256, DSM>>>(
        xc, wt_attn, b_attn, present, nullptr, BB * SS, 3 * NXX, NXX);
    // visual: [392,1024] @ [1024,2048]
    mma_gemm<1><<<dim3(2048 / 128, 4), 256, DSM>>>(
        vc, wt_vis, b_vis, present, nullptr, BB * NVV, 2 * NXX, 1024);
    // tags: [112,416] @ [416,2048]
    mma_gemm<2><<<dim3(2048 / 128, 1), 256, DSM>>>(
        tc, wtg, b_tags, present, nullptr, BB * NTT, 2 * NXX, KTAG);
    // attention
    attn_mma<<<dim3(SS / 64, HH, BB), 128, DSM_ATTN>>>();
    // proj: [8192,1024] @ [1024,1024]
    mma_gemm<3><<<dim3(1024 / 128, 8192 / 128), 256, DSM>>>(
        ga, wt_proj, b_proj, nullptr, out, BB * SS, NXX, NXX);
}

// round 17
// speedup vs baseline: 1.2156x; 1.0087x over previous
#include <cuda_runtime.h>
#include <cstdint>

// Problem constants
#define BB   8
#define SS   1024
#define NXX  1024
#define HH   16
#define DHH  64
#define NVV  49
#define NTT  14
#define NSS  1087          // 14 + 49 + 1024
#define NSSP 1088          // padded stride for g_kv (padding row stays zero)
#define PREF 63            // tags + visual prefix length
#define KTAG 416           // tags K padded 400 -> 416 (multiple of 32)

// Scratch (device globals: allocation-free per harness rules)
__device__ float g_q[(size_t)BB * HH * SS * DHH];       // Q, pre-scaled+tf32
__device__ float g_a[(size_t)BB * SS * NXX];            // attn out (tf32-rounded)
__device__ float g_wt[(size_t)6144 * 1024];             // tf32 weights, TRANSPOSED [N][K]
__device__ float g_wtg[(size_t)2048 * KTAG];            // tf32 W_tags^T [2048][416]
__device__ float g_tc[(size_t)BB * NTT * KTAG];         // tf32 tags, K-padded
__device__ float g_xc[(size_t)BB * SS * NXX];           // tf32 x
__device__ float g_vc[(size_t)BB * NVV * 1024];         // tf32 visual
__device__ float g_kv[(size_t)BB * 2 * HH * NSSP * DHH];// tf32 K/V, padded stride
#define OFF_WT_ATTN 0
#define OFF_WT_VIS  (3072 * 1024)
#define OFF_WT_PROJ (5120 * 1024)

// ---------------------------------------------------------------------------
__device__ __forceinline__ uint32_t f2tf32(float x) {
    uint32_t y;
    asm("cvt.rna.tf32.f32 %0, %1;" : "=r"(y) : "f"(x));
    return y;
}

__device__ __forceinline__ void mma_tf32(float* c, const uint32_t* a, const uint32_t* b) {
    asm volatile(
        "mma.sync.aligned.m16n8k8.row.col.f32.tf32.tf32.f32 "
        "{%0,%1,%2,%3}, {%4,%5,%6,%7}, {%8,%9}, {%0,%1,%2,%3};\n"
        : "+f"(c[0]), "+f"(c[1]), "+f"(c[2]), "+f"(c[3])
        : "r"(a[0]), "r"(a[1]), "r"(a[2]), "r"(a[3]), "r"(b[0]), "r"(b[1]));
}

__device__ __forceinline__ void ldsm_x4(uint32_t* r, uint32_t addr) {
    asm volatile(
        "ldmatrix.sync.aligned.m8n8.x4.shared.b16 {%0,%1,%2,%3}, [%4];"
        : "=r"(r[0]), "=r"(r[1]), "=r"(r[2]), "=r"(r[3]) : "r"(addr));
}

__device__ __forceinline__ uint32_t smem_u32(const void* p) {
    uint32_t a;
    asm("{ .reg .u64 t; cvta.to.shared.u64 t, %1; cvt.u32.u64 %0, t; }"
        : "=r"(a) : "l"(p));
    return a;
}

// ---------------------------------------------------------------------------
// Prep: tiled transpose + tf32 cvt.  in W[k][n] (Kin real rows) -> out Wt[n][k]
// ---------------------------------------------------------------------------
__global__ __launch_bounds__(256) void transpose_cvt(
    const float* __restrict__ in, float* __restrict__ out, int K, int N, int Kin)
{
    __shared__ float t[32][33];
    int k0 = blockIdx.x * 32, n0 = blockIdx.y * 32;
    int tx = threadIdx.x & 31, ty = threadIdx.x >> 5;
#pragma unroll
    for (int r = 0; r < 4; r++) {
        int k = k0 + ty + 8 * r;
        t[ty + 8 * r][tx] = (k < Kin) ? in[(size_t)k * N + n0 + tx] : 0.f;
    }
    __syncthreads();
#pragma unroll
    for (int r = 0; r < 4; r++)
        out[(size_t)(n0 + ty + 8 * r) * K + k0 + tx] =
            __uint_as_float(f2tf32(t[tx][ty + 8 * r]));
}

// Activation tf32 cvt (x + vis merged, block dispatch)
__global__ __launch_bounds__(256) void cvt_act(
    const float* s0, float* d0, int b0, const float* s1, float* d1)
{
    int blk = blockIdx.x;
    const float* src; float* dst;
    if (blk < b0) { src = s0; dst = d0; } else { blk -= b0; src = s1; dst = d1; }
    size_t i = ((size_t)blk * 256 + threadIdx.x) * 4;
    float4 v = *(const float4*)(src + i);
    uint4 p;
    p.x = f2tf32(v.x); p.y = f2tf32(v.y);
    p.z = f2tf32(v.z); p.w = f2tf32(v.w);
    *(uint4*)(dst + i) = p;
}

// tags pad+cvt: [112,400] -> [112,416] tf32 (cols >=400 zero)
__global__ __launch_bounds__(256) void pad_tags(const float* __restrict__ in)
{
    size_t i = ((size_t)blockIdx.x * 256 + threadIdx.x) * 4;
    if (i >= (size_t)BB * NTT * KTAG) return;
    int r = (int)(i / KTAG), c = (int)(i % KTAG);
    uint4 p = make_uint4(0u, 0u, 0u, 0u);
    if (c < 400) {
        float4 v = *(const float4*)(in + (size_t)r * 400 + c);
        p.x = f2tf32(v.x); p.y = f2tf32(v.y);
        p.z = f2tf32(v.z); p.w = f2tf32(v.w);
    }
    *(uint4*)(g_tc + i) = p;
}

// ---------------------------------------------------------------------------
// scatter helper
// ---------------------------------------------------------------------------
template <int MODE>
__device__ __forceinline__ void scatter(int r, int c, float val,
                                        float* __restrict__ present,
                                        float* __restrict__ outp)
{
    if (MODE == 0) {
        int b = r >> 10, s = r & 1023;
        int sect = c >> 10, cc = c & 1023;
        int h = cc >> 6, d = cc & 63;
        if (sect == 0) {
            g_q[((((size_t)b * HH + h) * SS + s) << 6) + d] =
                __uint_as_float(f2tf32(val * 0.125f));
        } else {
            present[(((((size_t)b * 2 + (sect - 1)) * HH + h) * NSS +
                      (PREF + s)) << 6) + d] = val;
            g_kv[(((((size_t)b * 2 + (sect - 1)) * HH + h) * NSSP +
                   (PREF + s)) << 6) + d] = __uint_as_float(f2tf32(val));
        }
    } else if (MODE == 1) {
        int b = r / NVV, p = r % NVV;
        int sect = c >> 10, cc = c & 1023;
        int h = cc >> 6, d = cc & 63;
        present[(((((size_t)b * 2 + sect) * HH + h) * NSS + (NTT + p)) << 6) + d] = val;
        g_kv[(((((size_t)b * 2 + sect) * HH + h) * NSSP + (NTT + p)) << 6) + d] =
            __uint_as_float(f2tf32(val));
    } else if (MODE == 2) {
        int b = r / NTT, p = r % NTT;
        int sect = c >> 10, cc = c & 1023;
        int h = cc >> 6, d = cc & 63;
        present[(((((size_t)b * 2 + sect) * HH + h) * NSS + p) << 6) + d] = val;
        g_kv[(((((size_t)b * 2 + sect) * HH + h) * NSSP + p) << 6) + d] =
            __uint_as_float(f2tf32(val));
    } else {
        outp[(size_t)r * NXX + c] = val;
    }
}

// ---------------------------------------------------------------------------
// tf32 mma GEMM, ldmatrix fragments, cp.async 2-stage pipeline (round-16).
// ---------------------------------------------------------------------------
template <int MODE>
__global__ __launch_bounds__(256, 2) void mma_gemm(
    const float* __restrict__ A, const float* __restrict__ Wt,
    const float* __restrict__ bias, float* __restrict__ present,
    float* __restrict__ outp, int M, int N, int K)
{
    extern __shared__ uint32_t sm[];
    const int bm = blockIdx.y, bn = blockIdx.x;
    const int tid = threadIdx.x;
    const int warp = tid >> 5, lane = tid & 31;
    const int wm = warp >> 1, wn = warp & 1;
    const int lq = lane >> 2, lr = lane & 3;

    const uint32_t sbase = smem_u32(sm);

    auto issue = [&](int s, int kt) {
        uint32_t abase = sbase + s * 36864;
        uint32_t bbase = abase + 18432;
#pragma unroll
        for (int i = 0; i < 4; i++) {
            int flat = tid + 256 * i;
            int m = flat >> 3, kc = flat & 7;
            int gm = bm * 128 + m;
            const float* src = A + (size_t)gm * K + kt + kc * 4;
            uint32_t dst = abase + m * 144 + kc * 16;
            int sz = (gm < M) ? 16 : 0;
            asm volatile("cp.async.ca.shared.global [%0], [%1], 16, %2;"
                         :: "r"(dst), "l"(src), "r"(sz));
        }
#pragma unroll
        for (int i = 0; i < 4; i++) {
            int flat = tid + 256 * i;
            int n = flat >> 3, kc = flat & 7;
            const float* src = Wt + (size_t)(bn * 128 + n) * K + kt + kc * 4;
            uint32_t dst = bbase + n * 144 + kc * 16;
            asm volatile("cp.async.ca.shared.global [%0], [%1], 16;"
                         :: "r"(dst), "l"(src));
        }
        asm volatile("cp.async.commit_group;");
    };

    const int lt = lane >> 3, rr = lane & 7;
    const uint32_t aoff = (uint32_t)(((wm * 32 + (lt & 1) * 8 + rr) * 36 +
                                      (lt >> 1) * 4) * 4);
    const uint32_t boff = (uint32_t)(((wn * 64 + (lt >> 1) * 8 + rr) * 36 +
                                      (lt & 1) * 4) * 4);

    float acc[2][8][4];
#pragma unroll
    for (int mt = 0; mt < 2; mt++)
#pragma unroll
        for (int nt = 0; nt < 8; nt++)
#pragma unroll
            for (int u = 0; u < 4; u++) acc[mt][nt][u] = 0.f;

    const int NC = K >> 5;
    issue(0, 0);
    if (NC > 1) issue(1, 32);
    else asm volatile("cp.async.commit_group;");

    for (int c = 0; c < NC; c++) {
        const int s = c & 1;
        asm volatile("cp.async.wait_group 1;" ::: "memory");
        __syncthreads();

        const uint32_t stA = sbase + s * 36864;
        const uint32_t stB = stA + 18432;

#pragma unroll
        for (int g = 0; g < 4; g++) {
            uint32_t af[2][4];
            ldsm_x4(af[0], stA + aoff + g * 32);
            ldsm_x4(af[1], stA + aoff + 2304 + g * 32);
            uint32_t bf[8][2];
#pragma unroll
            for (int p = 0; p < 4; p++) {
                uint32_t tmp[4];
                ldsm_x4(tmp, stB + boff + p * 2304 + g * 32);
                bf[2 * p][0] = tmp[0]; bf[2 * p][1] = tmp[1];
                bf[2 * p + 1][0] = tmp[2]; bf[2 * p + 1][1] = tmp[3];
            }
#pragma unroll
            for (int mt = 0; mt < 2; mt++)
#pragma unroll
                for (int nt = 0; nt < 8; nt++)
                    mma_tf32(acc[mt][nt], af[mt], bf[nt]);
        }
        __syncthreads();
        if (c + 2 < NC) issue(s, (c + 2) << 5);
        else asm volatile("cp.async.commit_group;");
    }

#pragma unroll
    for (int mt = 0; mt < 2; mt++) {
        int r0 = bm * 128 + wm * 32 + mt * 16 + lq;
#pragma unroll
        for (int nt = 0; nt < 8; nt++) {
            int c0 = bn * 128 + wn * 64 + nt * 8 + (lr << 1);
            float bz0 = bias[c0], bz1 = bias[c0 + 1];
            if (r0 < M) {
                scatter<MODE>(r0, c0,     acc[mt][nt][0] + bz0, present, outp);
                scatter<MODE>(r0, c0 + 1, acc[mt][nt][1] + bz1, present, outp);
            }
            if (r0 + 8 < M) {
                scatter<MODE>(r0 + 8, c0,     acc[mt][nt][2] + bz0, present, outp);
                scatter<MODE>(r0 + 8, c0 + 1, acc[mt][nt][3] + bz1, present, outp);
            }
        }
    }
}

// ---------------------------------------------------------------------------
// Flash attention v8: v7 + ldmatrix K fragments (4 LDSM.x4 per k-step replace
// 16 scalar LDS).  Q in registers, single-barrier double-buffered K/V.
// K stride 76 (LDSM tile rows at banks 12*rr: conflict-free), V stride 72.
// smem: 2 x (K 64x76 + V 64x72) = 75776 B -> 3 CTAs/SM.
// ---------------------------------------------------------------------------
#define KST 76
#define VST 72
#define KTW (64 * KST)
#define VTW (64 * VST)
#define PAIRW (KTW + VTW)

__global__ __launch_bounds__(128, 3) void attn_mma()
{
    extern __shared__ uint32_t sm[];
    const int qt = (int)(gridDim.x - 1) - blockIdx.x;
    const int h = blockIdx.y, b = blockIdx.z;
    const int tid = threadIdx.x;
    const int warp = tid >> 5, lane = tid & 31;
    const int lq = lane >> 2, lr = lane & 3;

    const float* qsrc  = g_q  + ((((size_t)b * HH + h) * SS + qt * 64) << 6);
    const char*  kbase = (const char*)(g_kv + (((((size_t)b * 2 + 0) * HH + h) * NSSP) << 6));
    const char*  vbase = (const char*)(g_kv + (((((size_t)b * 2 + 1) * HH + h) * NSSP) << 6));

    const uint32_t sbase = smem_u32(sm);
    const int tmax = qt + 1;

#pragma unroll
    for (int i = 0; i < 8; i++) {
        int c = tid + 128 * i;
        int row = c >> 4, q16 = (c & 15) << 4;
        asm volatile("cp.async.ca.shared.global [%0], [%1], 16;"
                     :: "r"(sbase + row * (KST * 4) + q16),
                        "l"((const char*)qsrc + (row << 8) + q16));
    }
    asm volatile("cp.async.commit_group;");
    asm volatile("cp.async.wait_group 0;" ::: "memory");
    __syncthreads();

    uint32_t Qf[8][4];
#pragma unroll
    for (int k0 = 0; k0 < 8; k0++) {
        const int rb = (warp * 16 + lq) * KST + k0 * 8;
        Qf[k0][0] = sm[rb + lr];
        Qf[k0][1] = sm[rb + 8 * KST + lr];
        Qf[k0][2] = sm[rb + lr + 4];
        Qf[k0][3] = sm[rb + 8 * KST + lr + 4];
    }
    __syncthreads();

    auto issue_tile = [&](int t) {
        const int s = t & 1;
        const uint32_t kd = sbase + s * PAIRW * 4;
        const uint32_t vd = kd + KTW * 4;
        const char* ks = kbase + ((size_t)t << 14);
        const char* vs = vbase + ((size_t)t << 14);
#pragma unroll
        for (int i = 0; i < 8; i++) {
            int c = tid + 128 * i;
            int row = c >> 4, q16 = (c & 15) << 4;
            int goff = (row << 8) + q16;
            asm volatile("cp.async.ca.shared.global [%0], [%1], 16;"
                         :: "r"(kd + row * (KST * 4) + q16), "l"(ks + goff));
            asm volatile("cp.async.ca.shared.global [%0], [%1], 16;"
                         :: "r"(vd + row * (VST * 4) + q16), "l"(vs + goff));
        }
        asm volatile("cp.async.commit_group;");
    };

    issue_tile(0);

    // ldmatrix lane offsets for K fragments (bytes within K tile):
    // tile p covers nt = 2p + (lt>>1), k-half = lt&1; rows rr.
    const int lt = lane >> 3, rr = lane & 7;
    uint32_t kfoff[4];
#pragma unroll
    for (int p = 0; p < 4; p++)
        kfoff[p] = (uint32_t)((((2 * p + (lt >> 1)) * 8 + rr) * KST +
                               (lt & 1) * 4) * 4);

    float Oa[8][4];
#pragma unroll
    for (int nd = 0; nd < 8; nd++)
#pragma unroll
        for (int u = 0; u < 4; u++) Oa[nd][u] = 0.f;
    float m0 = -1e30f, m1 = -1e30f, l0 = 0.f, l1 = 0.f;

    const int warp_r0 = qt * 64 + warp * 16;
    const int r0g = warp_r0 + lq;

    float Sa[8][4];

    for (int t = 0; t <= tmax; t++) {
        const int s = t & 1;
        const uint32_t stK = sbase + s * PAIRW * 4;
        const uint32_t* Vs = sm + s * PAIRW + KTW;

        asm volatile("cp.async.wait_group 0;" ::: "memory");
        __syncthreads();

        if (t + 1 <= tmax) issue_tile(t + 1);

        // ---- S = Q K^T (K fragments via ldmatrix) ----
#pragma unroll
        for (int nt = 0; nt < 8; nt++)
#pragma unroll
            for (int u = 0; u < 4; u++) Sa[nt][u] = 0.f;

#pragma unroll
        for (int k0 = 0; k0 < 8; k0++) {
            uint32_t bf[8][2];
#pragma unroll
            for (int p = 0; p < 4; p++) {
                uint32_t tmp[4];
                ldsm_x4(tmp, stK + kfoff[p] + k0 * 32);
                bf[2 * p][0] = tmp[0]; bf[2 * p][1] = tmp[1];
                bf[2 * p + 1][0] = tmp[2]; bf[2 * p + 1][1] = tmp[3];
            }
#pragma unroll
            for (int nt = 0; nt < 8; nt++)
                mma_tf32(Sa[nt], Qf[k0], bf[nt]);
        }

        if (t * 64 + 63 > warp_r0 + PREF) {
#pragma unroll
            for (int nt = 0; nt < 8; nt++) {
                int j0 = t * 64 + nt * 8 + (lr << 1);
                if (j0     > r0g + PREF     || j0     >= NSS) Sa[nt][0] = -1e30f;
                if (j0 + 1 > r0g + PREF     || j0 + 1 >= NSS) Sa[nt][1] = -1e30f;
                if (j0     > r0g + 8 + PREF || j0     >= NSS) Sa[nt][2] = -1e30f;
                if (j0 + 1 > r0g + 8 + PREF || j0 + 1 >= NSS) Sa[nt][3] = -1e30f;
            }
        }

        // ---- online softmax ----
        float mx0 = -1e30f, mx1 = -1e30f;
#pragma unroll
        for (int nt = 0; nt < 8; nt++) {
            mx0 = fmaxf(mx0, fmaxf(Sa[nt][0], Sa[nt][1]));
            mx1 = fmaxf(mx1, fmaxf(Sa[nt][2], Sa[nt][3]));
        }
        mx0 = fmaxf(mx0, __shfl_xor_sync(0xffffffffu, mx0, 1));
        mx0 = fmaxf(mx0, __shfl_xor_sync(0xffffffffu, mx0, 2));
        mx1 = fmaxf(mx1, __shfl_xor_sync(0xffffffffu, mx1, 1));
        mx1 = fmaxf(mx1, __shfl_xor_sync(0xffffffffu, mx1, 2));
        float mn0 = fmaxf(m0, mx0), mn1 = fmaxf(m1, mx1);
        float cr0 = __expf(m0 - mn0), cr1 = __expf(m1 - mn1);
        float s0 = 0.f, s1 = 0.f;
#pragma unroll
        for (int nt = 0; nt < 8; nt++) {
            float e0 = __expf(Sa[nt][0] - mn0); Sa[nt][0] = e0; s0 += e0;
            float e1 = __expf(Sa[nt][1] - mn0); Sa[nt][1] = e1; s0 += e1;
            float e2 = __expf(Sa[nt][2] - mn1); Sa[nt][2] = e2; s1 += e2;
            float e3 = __expf(Sa[nt][3] - mn1); Sa[nt][3] = e3; s1 += e3;
        }
        s0 += __shfl_xor_sync(0xffffffffu, s0, 1);
        s0 += __shfl_xor_sync(0xffffffffu, s0, 2);
        s1 += __shfl_xor_sync(0xffffffffu, s1, 1);
        s1 += __shfl_xor_sync(0xffffffffu, s1, 2);
        l0 = l0 * cr0 + s0; l1 = l1 * cr1 + s1;
        m0 = mn0; m1 = mn1;
#pragma unroll
        for (int nd = 0; nd < 8; nd++) {
            Oa[nd][0] *= cr0; Oa[nd][1] *= cr0;
            Oa[nd][2] *= cr1; Oa[nd][3] *= cr1;
        }

        // ---- O += P V ----
        const int sA = (lane & ~3) + (lr >> 1);
        const int sB = sA + 2;
        const bool odd = lr & 1;
#pragma unroll
        for (int kt = 0; kt < 8; kt++) {
            float p0 = __shfl_sync(0xffffffffu, Sa[kt][0], sA);
            float p1 = __shfl_sync(0xffffffffu, Sa[kt][1], sA);
            float p2 = __shfl_sync(0xffffffffu, Sa[kt][2], sA);
            float p3 = __shfl_sync(0xffffffffu, Sa[kt][3], sA);
            float q0 = __shfl_sync(0xffffffffu, Sa[kt][0], sB);
            float q1 = __shfl_sync(0xffffffffu, Sa[kt][1], sB);
            float q2 = __shfl_sync(0xffffffffu, Sa[kt][2], sB);
            float q3 = __shfl_sync(0xffffffffu, Sa[kt][3], sB);
            uint32_t a[4];
            a[0] = f2tf32(odd ? p1 : p0);
            a[1] = f2tf32(odd ? p3 : p2);
            a[2] = f2tf32(odd ? q1 : q0);
            a[3] = f2tf32(odd ? q3 : q2);
#pragma unroll
            for (int nd = 0; nd < 8; nd++) {
                uint32_t bf[2];
                const int vb = (kt * 8 + lr) * VST + nd * 8 + lq;
                bf[0] = Vs[vb];
                bf[1] = Vs[vb + 4 * VST];
                mma_tf32(Oa[nd], a, bf);
            }
        }
    }

    float inv0 = 1.f / l0, inv1 = 1.f / l1;
    float* ab = g_a + ((size_t)b * SS + qt * 64 + warp * 16) * NXX + h * 64;
#pragma unroll
    for (int nd = 0; nd < 8; nd++) {
        uint2 lo = make_uint2(f2tf32(Oa[nd][0] * inv0), f2tf32(Oa[nd][1] * inv0));
        uint2 hi = make_uint2(f2tf32(Oa[nd][2] * inv1), f2tf32(Oa[nd][3] * inv1));
        *(uint2*)&ab[(size_t)lq * NXX + nd * 8 + (lr << 1)] = lo;
        *(uint2*)&ab[(size_t)(lq + 8) * NXX + nd * 8 + (lr << 1)] = hi;
    }
}

// ---------------------------------------------------------------------------
extern "C" void kernel_launch(void* const* d_in, const int* in_sizes, int n_in,
                              void* d_out, int out_size)
{
    const float* x      = (const float*)d_in[0];
    const float* vis    = (const float*)d_in[1];
    const float* tags   = (const float*)d_in[2];
    const float* W_attn = (const float*)d_in[3];
    const float* b_attn = (const float*)d_in[4];
    const float* W_vis  = (const float*)d_in[5];
    const float* b_vis  = (const float*)d_in[6];
    const float* W_tags = (const float*)d_in[7];
    const float* b_tags = (const float*)d_in[8];
    const float* W_proj = (const float*)d_in[9];
    const float* b_proj = (const float*)d_in[10];

    float* out = (float*)d_out;
    float* present = out + (size_t)BB * SS * NXX;   // a first, then present

    static float *wt_base = nullptr, *xc = nullptr, *vc = nullptr, *ga = nullptr;
    static float *wtg = nullptr, *tc = nullptr;
    const int DSM = 73728;
    const int DSM_ATTN = 2 * PAIRW * 4;     // 75776
    if (!wt_base) {
        cudaGetSymbolAddress((void**)&wt_base, g_wt);
        cudaGetSymbolAddress((void**)&xc, g_xc);
        cudaGetSymbolAddress((void**)&vc, g_vc);
        cudaGetSymbolAddress((void**)&ga, g_a);
        cudaGetSymbolAddress((void**)&wtg, g_wtg);
        cudaGetSymbolAddress((void**)&tc, g_tc);
        cudaFuncSetAttribute(mma_gemm<0>, cudaFuncAttributeMaxDynamicSharedMemorySize, DSM);
        cudaFuncSetAttribute(mma_gemm<1>, cudaFuncAttributeMaxDynamicSharedMemorySize, DSM);
        cudaFuncSetAttribute(mma_gemm<2>, cudaFuncAttributeMaxDynamicSharedMemorySize, DSM);
        cudaFuncSetAttribute(mma_gemm<3>, cudaFuncAttributeMaxDynamicSharedMemorySize, DSM);
        cudaFuncSetAttribute(attn_mma, cudaFuncAttributeMaxDynamicSharedMemorySize, DSM_ATTN);
    }
    float* wt_attn = wt_base + OFF_WT_ATTN;
    float* wt_vis  = wt_base + OFF_WT_VIS;
    float* wt_proj = wt_base + OFF_WT_PROJ;

    // Prep: transpose+cvt weights; cvt activations; pad tags
    transpose_cvt<<<dim3(32, 96), 256>>>(W_attn, wt_attn, 1024, 3072, 1024);
    transpose_cvt<<<dim3(32, 64), 256>>>(W_vis,  wt_vis,  1024, 2048, 1024);
    transpose_cvt<<<dim3(32, 32), 256>>>(W_proj, wt_proj, 1024, 1024, 1024);
    transpose_cvt<<<dim3(KTAG / 32, 64), 256>>>(W_tags, wtg, KTAG, 2048, 400);
    cvt_act<<<8192 + 392, 256>>>(x, xc, 8192, vis, vc);
    pad_tags<<<(BB * NTT * KTAG + 1023) / 1024, 256>>>(tags);

    // QKV: [8192,1024] @ [1024,3072]
    mma_gemm<0><<<dim3(3072 / 128, 8192 / 128), 256, DSM>>>(
        xc, wt_attn, b_attn, present, nullptr, BB * SS, 3 * NXX, NXX);
    // visual: [392,1024] @ [1024,2048]
    mma_gemm<1><<<dim3(2048 / 128, 4), 256, DSM>>>(
        vc, wt_vis, b_vis, present, nullptr, BB * NVV, 2 * NXX, 1024);
    // tags: [112,416] @ [416,2048]
    mma_gemm<2><<<dim3(2048 / 128, 1), 256, DSM>>>(
        tc, wtg, b_tags, present, nullptr, BB * NTT, 2 * NXX, KTAG);
    // attention (ldmatrix K fragments)
    attn_mma<<<dim3(SS / 64, HH, BB), 128, DSM_ATTN>>>();
    // proj: [8192,1024] @ [1024,1024]
    mma_gemm<3><<<dim3(1024 / 128, 8192 / 128), 256, DSM>>>(
        ga, wt_proj, b_proj, nullptr, out, BB * SS, NXX, NXX);
}